// round 1
// baseline (speedup 1.0000x reference)
#include <cuda_runtime.h>
#include <math.h>

// ---------------------------------------------------------------------------
// TimeKAN forward. B=128, D=128, LENS={512,256,128,64}, ORDERS={1,2,3,4}.
// freq_interp == batched GEMM with a precomputed Dirichlet-kernel matrix.
// cheby_kan == GEMM over Chebyshev basis T_k(tanh(tanh(x))).
// dw_conv fused into m_kan GEMM epilogue.
// ---------------------------------------------------------------------------

#define OFF512 0
#define OFF256 8388608
#define OFF128 12582912
#define OFF64  14680064

// interp weight matrices (2L x L)
__device__ float g_W64 [128 *  64];
__device__ float g_W128[256 * 128];
__device__ float g_W256[512 * 256];

// transposed coeffs: Ct[(k*128+i)*128 + o] = coeffs[i,o,k]
__device__ float g_Ct0[2 * 128 * 128];
__device__ float g_Ct1[3 * 128 * 128];
__device__ float g_Ct2[4 * 128 * 128];
__device__ float g_Ct3[5 * 128 * 128];

// dec outputs
__device__ float g_d1[128 * 128 * 128];
__device__ float g_d2[128 * 256 * 128];
__device__ float g_d3[128 * 512 * 128];

// m_kan outputs of the high branches
__device__ float g_oh1[128 * 128 * 128];
__device__ float g_oh2[128 * 256 * 128];
__device__ float g_oh3[128 * 512 * 128];

// reusable Chebyshev basis buffer (max: M=65536, K'=640)
__device__ float g_basis[41943040];

// ---------------------------------------------------------------------------
// Fill interp matrix W (2L x L):
//  even row m=2n': 0.25*delta(n,n') + (-1)^(n+n')/(4L)
//  odd  row:       g(t)/(4L), t=m-2n, g(t)=sin((L+1)*pi*t/(2L))/sin(pi*t/(2L))
// ---------------------------------------------------------------------------
__global__ void fill_W_kernel(float* __restrict__ W, int L) {
    int idx = blockIdx.x * blockDim.x + threadIdx.x;
    int total = 2 * L * L;
    if (idx >= total) return;
    int m = idx / L;
    int n = idx - m * L;
    float inv4L = 0.25f / (float)L;
    float val;
    if ((m & 1) == 0) {
        int np = m >> 1;
        val = (((np + n) & 1) ? -inv4L : inv4L);
        if (n == np) val += 0.25f;
    } else {
        int t = m - 2 * n;               // odd, in (-2L, 2L)
        double th = (double)t * M_PI / (2.0 * (double)L);
        double g = sin((double)(L + 1) * th) / sin(th);
        val = (float)(g * 0.25 / (double)L);
    }
    W[idx] = val;
}

// Ct[(k*128+i)*128+o] = coeffs[(i*128+o)*K + k]
__global__ void transpose_coeffs_kernel(const float* __restrict__ c,
                                        float* __restrict__ Ct, int K) {
    int idx = blockIdx.x * blockDim.x + threadIdx.x;
    int total = K * 128 * 128;
    if (idx >= total) return;
    int o = idx & 127;
    int i = (idx >> 7) & 127;
    int k = idx >> 14;
    Ct[idx] = c[(i * 128 + o) * K + k];
}

// basis[m*Kp + k*128 + i] = T_k(tanh(tanh(src[m*128+i]))), k=0..K-1
__global__ void basis_kernel(const float* __restrict__ src,
                             float* __restrict__ basis, int M, int K) {
    int idx = blockIdx.x * blockDim.x + threadIdx.x;
    if (idx >= M * 128) return;
    int m = idx >> 7;
    int i = idx & 127;
    float u = tanhf(tanhf(src[idx]));
    int Kp = K * 128;
    int base = m * Kp + i;
    float t0 = 1.0f, t1 = u;
    basis[base] = 1.0f;
    basis[base + 128] = u;
    for (int k = 2; k < K; k++) {
        float t2 = 2.0f * u * t1 - t0;
        basis[base + k * 128] = t2;
        t0 = t1; t1 = t2;
    }
}

// ---------------------------------------------------------------------------
// interp GEMM: out[b,m,:] = base[b,m,:] + alpha * sum_n W[m,n]*xin[b,n,:]
// Per batch: (2L x L) x (L x 128). Grid: (2L/64, B). Block 256, 4x8/thread.
// ---------------------------------------------------------------------------
__global__ __launch_bounds__(256)
void interp_kernel(const float* __restrict__ W, const float* __restrict__ xin,
                   const float* __restrict__ base, float* __restrict__ out,
                   int L, float alpha) {
    __shared__ float As[16][64];
    __shared__ float Bs[16][128];

    int b  = blockIdx.y;
    int m0 = blockIdx.x * 64;
    int tid = threadIdx.x;
    int tx = tid & 15;
    int ty = tid >> 4;

    const float* xb = xin + b * L * 128;

    float acc[4][8];
#pragma unroll
    for (int r = 0; r < 4; r++)
#pragma unroll
        for (int c = 0; c < 8; c++) acc[r][c] = 0.0f;

    for (int k0 = 0; k0 < L; k0 += 16) {
#pragma unroll
        for (int e = 0; e < 4; e++) {
            int idx = tid + e * 256;
            int r = idx >> 4, c = idx & 15;
            As[c][r] = W[(m0 + r) * L + k0 + c];
        }
#pragma unroll
        for (int e = 0; e < 8; e++) {
            int idx = tid + e * 256;
            int r = idx >> 7, c = idx & 127;
            Bs[r][c] = xb[(k0 + r) * 128 + c];
        }
        __syncthreads();
#pragma unroll
        for (int kk = 0; kk < 16; kk++) {
            float4 a4 = *(const float4*)&As[kk][ty * 4];
            float4 p  = *(const float4*)&Bs[kk][tx * 8];
            float4 q  = *(const float4*)&Bs[kk][tx * 8 + 4];
            float av[4] = {a4.x, a4.y, a4.z, a4.w};
            float bv[8] = {p.x, p.y, p.z, p.w, q.x, q.y, q.z, q.w};
#pragma unroll
            for (int r = 0; r < 4; r++)
#pragma unroll
                for (int c = 0; c < 8; c++)
                    acc[r][c] = fmaf(av[r], bv[c], acc[r][c]);
        }
        __syncthreads();
    }

    int TL = 2 * L;
    int row = m0 + ty * 4;
    int colb = tx * 8;
#pragma unroll
    for (int r = 0; r < 4; r++) {
        int off = (b * TL + row + r) * 128 + colb;
        float4 b0 = *(const float4*)&base[off];
        float4 b1 = *(const float4*)&base[off + 4];
        float4 o0, o1;
        o0.x = fmaf(alpha, acc[r][0], b0.x);
        o0.y = fmaf(alpha, acc[r][1], b0.y);
        o0.z = fmaf(alpha, acc[r][2], b0.z);
        o0.w = fmaf(alpha, acc[r][3], b0.w);
        o1.x = fmaf(alpha, acc[r][4], b1.x);
        o1.y = fmaf(alpha, acc[r][5], b1.y);
        o1.z = fmaf(alpha, acc[r][6], b1.z);
        o1.w = fmaf(alpha, acc[r][7], b1.w);
        *(float4*)&out[off]     = o0;
        *(float4*)&out[off + 4] = o1;
    }
}

// ---------------------------------------------------------------------------
// m_kan GEMM: out[m,o] = sum_c A[m,c]*Ct[c,o] + depthwise-conv3(x, w) epilogue
// A: (M x Kp) Chebyshev basis, Ct: (Kp x 128). Grid: M/64. Block 256.
// ---------------------------------------------------------------------------
__global__ __launch_bounds__(256)
void mkan_kernel(const float* __restrict__ A, const float* __restrict__ Ct,
                 const float* __restrict__ x, const float* __restrict__ w,
                 float* __restrict__ out, int M, int Kp, int Ntime) {
    __shared__ float As[16][64];
    __shared__ float Bs[16][128];
    __shared__ float Ws[384];

    int m0 = blockIdx.x * 64;
    int tid = threadIdx.x;
    int tx = tid & 15;
    int ty = tid >> 4;

    for (int j = tid; j < 384; j += 256) Ws[j] = w[j];

    float acc[4][8];
#pragma unroll
    for (int r = 0; r < 4; r++)
#pragma unroll
        for (int c = 0; c < 8; c++) acc[r][c] = 0.0f;

    for (int k0 = 0; k0 < Kp; k0 += 16) {
#pragma unroll
        for (int e = 0; e < 4; e++) {
            int idx = tid + e * 256;
            int r = idx >> 4, c = idx & 15;
            As[c][r] = A[(m0 + r) * Kp + k0 + c];
        }
#pragma unroll
        for (int e = 0; e < 8; e++) {
            int idx = tid + e * 256;
            int r = idx >> 7, c = idx & 127;
            Bs[r][c] = Ct[(k0 + r) * 128 + c];
        }
        __syncthreads();
#pragma unroll
        for (int kk = 0; kk < 16; kk++) {
            float4 a4 = *(const float4*)&As[kk][ty * 4];
            float4 p  = *(const float4*)&Bs[kk][tx * 8];
            float4 q  = *(const float4*)&Bs[kk][tx * 8 + 4];
            float av[4] = {a4.x, a4.y, a4.z, a4.w};
            float bv[8] = {p.x, p.y, p.z, p.w, q.x, q.y, q.z, q.w};
#pragma unroll
            for (int r = 0; r < 4; r++)
#pragma unroll
                for (int c = 0; c < 8; c++)
                    acc[r][c] = fmaf(av[r], bv[c], acc[r][c]);
        }
        __syncthreads();
    }

    int row = m0 + ty * 4;
    int colb = tx * 8;
#pragma unroll
    for (int r = 0; r < 4; r++) {
        int m = row + r;
        int n = m & (Ntime - 1);
        int off = m * 128 + colb;

        float cur[8], prv[8], nxt[8];
        {
            float4 a = *(const float4*)&x[off];
            float4 c4 = *(const float4*)&x[off + 4];
            cur[0]=a.x; cur[1]=a.y; cur[2]=a.z; cur[3]=a.w;
            cur[4]=c4.x; cur[5]=c4.y; cur[6]=c4.z; cur[7]=c4.w;
        }
        if (n > 0) {
            float4 a = *(const float4*)&x[off - 128];
            float4 c4 = *(const float4*)&x[off - 128 + 4];
            prv[0]=a.x; prv[1]=a.y; prv[2]=a.z; prv[3]=a.w;
            prv[4]=c4.x; prv[5]=c4.y; prv[6]=c4.z; prv[7]=c4.w;
        } else {
#pragma unroll
            for (int c = 0; c < 8; c++) prv[c] = 0.0f;
        }
        if (n < Ntime - 1) {
            float4 a = *(const float4*)&x[off + 128];
            float4 c4 = *(const float4*)&x[off + 128 + 4];
            nxt[0]=a.x; nxt[1]=a.y; nxt[2]=a.z; nxt[3]=a.w;
            nxt[4]=c4.x; nxt[5]=c4.y; nxt[6]=c4.z; nxt[7]=c4.w;
        } else {
#pragma unroll
            for (int c = 0; c < 8; c++) nxt[c] = 0.0f;
        }

        float res[8];
#pragma unroll
        for (int c = 0; c < 8; c++) {
            int o = colb + c;
            float v = acc[r][c];
            v = fmaf(cur[c], Ws[o * 3 + 1], v);
            v = fmaf(prv[c], Ws[o * 3 + 0], v);
            v = fmaf(nxt[c], Ws[o * 3 + 2], v);
            res[c] = v;
        }
        float4 o0 = {res[0], res[1], res[2], res[3]};
        float4 o1 = {res[4], res[5], res[6], res[7]};
        *(float4*)&out[off]     = o0;
        *(float4*)&out[off + 4] = o1;
    }
}

// ---------------------------------------------------------------------------
extern "C" void kernel_launch(void* const* d_in, const int* in_sizes, int n_in,
                              void* d_out, int out_size) {
    const float* x0 = (const float*)d_in[0];   // (128,512,128)
    const float* x1 = (const float*)d_in[1];   // (128,256,128)
    const float* x2 = (const float*)d_in[2];   // (128,128,128)
    const float* x3 = (const float*)d_in[3];   // (128, 64,128)
    const float* c0 = (const float*)d_in[4];
    const float* w0 = (const float*)d_in[5];
    const float* c1 = (const float*)d_in[6];
    const float* w1 = (const float*)d_in[7];
    const float* c2 = (const float*)d_in[8];
    const float* w2 = (const float*)d_in[9];
    const float* c3 = (const float*)d_in[10];
    const float* w3 = (const float*)d_in[11];
    float* out = (float*)d_out;

    float *pW64, *pW128, *pW256, *pCt0, *pCt1, *pCt2, *pCt3;
    float *pd1, *pd2, *pd3, *poh1, *poh2, *poh3, *pbasis;
    cudaGetSymbolAddress((void**)&pW64,  g_W64);
    cudaGetSymbolAddress((void**)&pW128, g_W128);
    cudaGetSymbolAddress((void**)&pW256, g_W256);
    cudaGetSymbolAddress((void**)&pCt0,  g_Ct0);
    cudaGetSymbolAddress((void**)&pCt1,  g_Ct1);
    cudaGetSymbolAddress((void**)&pCt2,  g_Ct2);
    cudaGetSymbolAddress((void**)&pCt3,  g_Ct3);
    cudaGetSymbolAddress((void**)&pd1,   g_d1);
    cudaGetSymbolAddress((void**)&pd2,   g_d2);
    cudaGetSymbolAddress((void**)&pd3,   g_d3);
    cudaGetSymbolAddress((void**)&poh1,  g_oh1);
    cudaGetSymbolAddress((void**)&poh2,  g_oh2);
    cudaGetSymbolAddress((void**)&poh3,  g_oh3);
    cudaGetSymbolAddress((void**)&pbasis, g_basis);

    // --- setup: interp matrices + coeff transposes ---
    fill_W_kernel<<<(2*64*64   + 255) / 256, 256>>>(pW64,  64);
    fill_W_kernel<<<(2*128*128 + 255) / 256, 256>>>(pW128, 128);
    fill_W_kernel<<<(2*256*256 + 255) / 256, 256>>>(pW256, 256);
    transpose_coeffs_kernel<<<(2*128*128 + 255) / 256, 256>>>(c0, pCt0, 2);
    transpose_coeffs_kernel<<<(3*128*128 + 255) / 256, 256>>>(c1, pCt1, 3);
    transpose_coeffs_kernel<<<(4*128*128 + 255) / 256, 256>>>(c2, pCt2, 4);
    transpose_coeffs_kernel<<<(5*128*128 + 255) / 256, 256>>>(c3, pCt3, 5);

    // --- decomposition: d_k = x_high - interp(x_low) ---
    { dim3 g(128 / 64, 128);  interp_kernel<<<g, 256>>>(pW64,  x3, x2, pd1,  64, -1.0f); }
    { dim3 g(256 / 64, 128);  interp_kernel<<<g, 256>>>(pW128, x2, x1, pd2, 128, -1.0f); }
    { dim3 g(512 / 64, 128);  interp_kernel<<<g, 256>>>(pW256, x1, x0, pd3, 256, -1.0f); }

    // --- m_kan stages (basis -> GEMM + fused dwconv) ---
    // stage 0: x3 -> mix64 (final output, also input to mix chain)
    {
        int M = 128 * 64;
        basis_kernel<<<(M * 128 + 255) / 256, 256>>>(x3, pbasis, M, 2);
        mkan_kernel<<<M / 64, 256>>>(pbasis, pCt0, x3, w0, out + OFF64, M, 2 * 128, 64);
    }
    // stage 1: d1 -> oh1
    {
        int M = 128 * 128;
        basis_kernel<<<(M * 128 + 255) / 256, 256>>>(pd1, pbasis, M, 3);
        mkan_kernel<<<M / 64, 256>>>(pbasis, pCt1, pd1, w1, poh1, M, 3 * 128, 128);
    }
    // stage 2: d2 -> oh2
    {
        int M = 128 * 256;
        basis_kernel<<<(M * 128 + 255) / 256, 256>>>(pd2, pbasis, M, 4);
        mkan_kernel<<<M / 64, 256>>>(pbasis, pCt2, pd2, w2, poh2, M, 4 * 128, 256);
    }
    // stage 3: d3 -> oh3
    {
        int M = 128 * 512;
        basis_kernel<<<(M * 128 + 255) / 256, 256>>>(pd3, pbasis, M, 5);
        mkan_kernel<<<M / 64, 256>>>(pbasis, pCt3, pd3, w3, poh3, M, 5 * 128, 512);
    }

    // --- mix chain: mix_l = oh_l + interp(mix_{l-1}) ---
    { dim3 g(128 / 64, 128);  interp_kernel<<<g, 256>>>(pW64,  out + OFF64,  poh1, out + OFF128,  64, 1.0f); }
    { dim3 g(256 / 64, 128);  interp_kernel<<<g, 256>>>(pW128, out + OFF128, poh2, out + OFF256, 128, 1.0f); }
    { dim3 g(512 / 64, 128);  interp_kernel<<<g, 256>>>(pW256, out + OFF256, poh3, out + OFF512, 256, 1.0f); }

    (void)in_sizes; (void)n_in; (void)out_size;
}

// round 3
// speedup vs baseline: 2.7285x; 2.7285x over previous
#include <cuda_runtime.h>
#include <math.h>
#include <cstdint>

// ---------------------------------------------------------------------------
// TimeKAN forward, mma.sync tf32 edition (plain sm_103 target — no tcgen05).
// B=128, D=128, LENS={512,256,128,64}, ORDERS={1,2,3,4}.
// freq_interp == batched GEMM with precomputed Dirichlet matrix.
// cheby_kan == GEMM over T_k(tanh(tanh(x))) with T_0 folded into a bias.
// dw_conv fused into the m_kan epilogue.
// ---------------------------------------------------------------------------

#define OFF512 0
#define OFF256 8388608
#define OFF128 12582912
#define OFF64  14680064

// interp weight matrices (2L x L), row-major (K-contiguous)
__device__ float g_W64 [128 *  64];
__device__ float g_W128[256 * 128];
__device__ float g_W256[512 * 256];

// B operands for mkan, K-contiguous: CtT[o*Kp + k*128 + i] = coeffs[i,o,k]
__device__ float g_Ct0[128 * 256];
__device__ float g_Ct1[128 * 384];
__device__ float g_Ct2[128 * 512];
__device__ float g_Ct3[128 * 640];
// bias[o] = sum_i coeffs[i,o,0]  (T_0 plane contribution)
__device__ float g_bias[4 * 128];

// dec outputs
__device__ float g_d1[128 * 128 * 128];
__device__ float g_d2[128 * 256 * 128];
__device__ float g_d3[128 * 512 * 128];

// m_kan outputs of the high branches
__device__ float g_oh1[128 * 128 * 128];
__device__ float g_oh2[128 * 256 * 128];
__device__ float g_oh3[128 * 512 * 128];

// u = tanh(tanh(x)) scratch (max M=65536 rows x 128)
__device__ float g_u[65536 * 128];
// transposed x scratch [b,128,L] (max L=512)
__device__ float g_xT[128 * 128 * 512];

// ---------------------------------------------------------------------------
// helpers
// ---------------------------------------------------------------------------
__device__ __forceinline__ uint32_t f2tf32(float f) {
    uint32_t r;
    asm("cvt.rna.tf32.f32 %0, %1;" : "=r"(r) : "f"(f));
    return r;
}

__device__ __forceinline__ void mma_tf32(float c[4], const uint32_t a[4],
                                         uint32_t b0, uint32_t b1) {
    asm volatile(
        "mma.sync.aligned.m16n8k8.row.col.f32.tf32.tf32.f32 "
        "{%0,%1,%2,%3}, {%4,%5,%6,%7}, {%8,%9}, {%0,%1,%2,%3};"
        : "+f"(c[0]), "+f"(c[1]), "+f"(c[2]), "+f"(c[3])
        : "r"(a[0]), "r"(a[1]), "r"(a[2]), "r"(a[3]), "r"(b0), "r"(b1));
}

__device__ __forceinline__ float chebT(int k, float uu) {
    if (k == 1) return uu;
    if (k == 2) return fmaf(2.0f * uu, uu, -1.0f);
    if (k == 3) return uu * fmaf(4.0f * uu, uu, -3.0f);
    float s = uu * uu;
    return fmaf(8.0f * s, s - 1.0f, 1.0f);   // k == 4
}

// Fragment-native smem staging.
// A (128 x 32) element (m, k):
//   frag = (m>>4)*4 + (k>>3); lane = (m&7)*4 + (k&3);
//   slot = ((m>>3)&1) + 2*((k>>2)&1); word index = frag*128 + lane*4 + slot.
// B (128 x 32) element (n, k):
//   frag = (n>>3)*4 + (k>>3); lane = (n&7)*4 + (k&3);
//   slot = (k>>2)&1;          word index = frag*64 + lane*2 + slot.
__device__ __forceinline__ void stageA4(uint32_t* SA, int m, int kb, float4 v) {
    int mf = m >> 4, r = m & 15;
    int kf = kb >> 1;
    int slot = (r >> 3) + ((kb & 1) << 1);
    uint32_t* p = SA + (mf * 4 + kf) * 128 + (r & 7) * 16 + slot;
    p[0]  = f2tf32(v.x);
    p[4]  = f2tf32(v.y);
    p[8]  = f2tf32(v.z);
    p[12] = f2tf32(v.w);
}
__device__ __forceinline__ void stageB4(uint32_t* SB, int n, int kb, float4 v) {
    int nf = n >> 3;
    int kf = kb >> 1;
    int slot = kb & 1;
    uint32_t* p = SB + (nf * 4 + kf) * 64 + (n & 7) * 8 + slot;
    p[0] = f2tf32(v.x);
    p[2] = f2tf32(v.y);
    p[4] = f2tf32(v.z);
    p[6] = f2tf32(v.w);
}

// ---------------------------------------------------------------------------
// setup kernels
// ---------------------------------------------------------------------------
__global__ void fill_W_kernel(float* __restrict__ W, int L) {
    int idx = blockIdx.x * blockDim.x + threadIdx.x;
    int total = 2 * L * L;
    if (idx >= total) return;
    int m = idx / L;
    int n = idx - m * L;
    float inv4L = 0.25f / (float)L;
    float val;
    if ((m & 1) == 0) {
        int np = m >> 1;
        val = (((np + n) & 1) ? -inv4L : inv4L);
        if (n == np) val += 0.25f;
    } else {
        int t = m - 2 * n;
        double th = (double)t * M_PI / (2.0 * (double)L);
        double g = sin((double)(L + 1) * th) / sin(th);
        val = (float)(g * 0.25 / (double)L);
    }
    W[idx] = val;
}

// CtT[o*Kp + k*128 + i] = coeffs[(i*128+o)*K + k]
__global__ void ctT_kernel(const float* __restrict__ c, float* __restrict__ CtT, int K) {
    int idx = blockIdx.x * blockDim.x + threadIdx.x;
    int Kp = K * 128;
    if (idx >= 128 * Kp) return;
    int o = idx / Kp;
    int cc = idx - o * Kp;
    int k = cc >> 7;
    int i = cc & 127;
    CtT[idx] = c[(i * 128 + o) * K + k];
}

__global__ void bias_kernel(const float* __restrict__ c, float* __restrict__ bias, int K) {
    int o = threadIdx.x;
    float s = 0.0f;
    for (int i = 0; i < 128; i++) s += c[(i * 128 + o) * K];
    bias[o] = s;
}

__global__ void u_kernel(const float* __restrict__ x, float* __restrict__ u, int total) {
    int i = blockIdx.x * blockDim.x + threadIdx.x;
    if (i < total) u[i] = tanhf(tanhf(x[i]));
}

// xT[b,o,n] = x[b,n,o]; grid (L/32, 4, B), block (32, 8)
__global__ void transpose_kernel(const float* __restrict__ x, float* __restrict__ xT, int L) {
    __shared__ float t[32][33];
    int b = blockIdx.z;
    int n0 = blockIdx.x * 32;
    int o0 = blockIdx.y * 32;
    int tx = threadIdx.x, ty = threadIdx.y;
    const float* xp = x + (size_t)b * L * 128;
    float* xq = xT + (size_t)b * 128 * L;
#pragma unroll
    for (int i = 0; i < 32; i += 8)
        t[ty + i][tx] = xp[(n0 + ty + i) * 128 + o0 + tx];
    __syncthreads();
#pragma unroll
    for (int i = 0; i < 32; i += 8)
        xq[(o0 + ty + i) * L + n0 + tx] = t[tx][ty + i];
}

// ---------------------------------------------------------------------------
// mkan GEMM: out[m,o] = bias[o] + sum_{k>=128} A[m,k]*CtT[o,k] + dwconv3(x,w)
// A[m, kk*128+i] = T_kk(u[m,i]), built on the fly. Grid: M/128. Block 256.
// ---------------------------------------------------------------------------
__global__ __launch_bounds__(256, 2)
void mkan_mma_kernel(const float* __restrict__ u, const float* __restrict__ Bm,
                     const float* __restrict__ bias, const float* __restrict__ x,
                     const float* __restrict__ w, float* __restrict__ out,
                     int Kp, int Ntime) {
    __shared__ uint32_t SA[4096];
    __shared__ uint32_t SB[4096];
    __shared__ float Ws[384];
    __shared__ float Bsh[128];

    int tid = threadIdx.x, lane = tid & 31, warp = tid >> 5;
    int wm = warp & 3, wn = warp >> 2;
    int g = lane >> 2, t4 = lane & 3;
    int m0 = blockIdx.x * 128;

    for (int j = tid; j < 384; j += 256) Ws[j] = w[j];
    if (tid < 128) Bsh[tid] = bias[tid];

    float acc[2][8][4];
#pragma unroll
    for (int r = 0; r < 2; r++)
#pragma unroll
        for (int nf = 0; nf < 8; nf++)
#pragma unroll
            for (int s = 0; s < 4; s++) acc[r][nf][s] = 0.0f;

    int nch = Kp >> 5;
    for (int ch = 4; ch < nch; ch++) {     // ch 0..3 (kk=0) folded into bias
        int k0 = ch << 5;
        int kk = k0 >> 7;
        int i0 = k0 & 127;
        __syncthreads();
#pragma unroll
        for (int e = 0; e < 4; e++) {
            int flat = e * 256 + tid;
            int row = flat >> 3, kb = flat & 7;
            float4 v = *(const float4*)(u + (size_t)(m0 + row) * 128 + i0 + kb * 4);
            float4 t;
            t.x = chebT(kk, v.x); t.y = chebT(kk, v.y);
            t.z = chebT(kk, v.z); t.w = chebT(kk, v.w);
            stageA4(SA, row, kb, t);
            float4 bv = *(const float4*)(Bm + (size_t)row * Kp + k0 + kb * 4);
            stageB4(SB, row, kb, bv);
        }
        __syncthreads();
#pragma unroll
        for (int ks = 0; ks < 4; ks++) {
            uint32_t a[2][4];
#pragma unroll
            for (int r = 0; r < 2; r++) {
                uint4 t = *(const uint4*)(SA + ((wm * 2 + r) * 4 + ks) * 128 + lane * 4);
                a[r][0] = t.x; a[r][1] = t.y; a[r][2] = t.z; a[r][3] = t.w;
            }
#pragma unroll
            for (int nf = 0; nf < 8; nf++) {
                uint2 bb = *(const uint2*)(SB + ((wn * 8 + nf) * 4 + ks) * 64 + lane * 2);
                mma_tf32(acc[0][nf], a[0], bb.x, bb.y);
                mma_tf32(acc[1][nf], a[1], bb.x, bb.y);
            }
        }
    }

    // epilogue: + bias + depthwise conv3(x)
    int cbase = wn * 64 + t4 * 2;
#pragma unroll
    for (int r = 0; r < 2; r++) {
#pragma unroll
        for (int h = 0; h < 2; h++) {
            int m = m0 + wm * 32 + r * 16 + h * 8 + g;
            int n = m & (Ntime - 1);
            const float* xr = x + (size_t)m * 128;
            float* orow = out + (size_t)m * 128;
            bool hasp = n > 0, hasn = n < (Ntime - 1);
#pragma unroll
            for (int nf = 0; nf < 8; nf++) {
                int c = cbase + nf * 8;
                float v0 = acc[r][nf][h * 2 + 0] + Bsh[c];
                float v1 = acc[r][nf][h * 2 + 1] + Bsh[c + 1];
                float2 cur = *(const float2*)(xr + c);
                float2 prv = hasp ? *(const float2*)(xr + c - 128) : make_float2(0.f, 0.f);
                float2 nxt = hasn ? *(const float2*)(xr + c + 128) : make_float2(0.f, 0.f);
                v0 += cur.x * Ws[c * 3 + 1] + prv.x * Ws[c * 3] + nxt.x * Ws[c * 3 + 2];
                v1 += cur.y * Ws[c * 3 + 4] + prv.y * Ws[c * 3 + 3] + nxt.y * Ws[c * 3 + 5];
                *(float2*)(orow + c) = make_float2(v0, v1);
            }
        }
    }
}

// ---------------------------------------------------------------------------
// interp GEMM: out[b,m,o] = base[b,m,o] + alpha * sum_n W[m,n]*xT[b,o,n]
// Grid: (2L/128, B). Block 256.
// ---------------------------------------------------------------------------
__global__ __launch_bounds__(256, 2)
void interp_mma_kernel(const float* __restrict__ W, const float* __restrict__ xT,
                       const float* __restrict__ base, float* __restrict__ out,
                       int L, float alpha) {
    __shared__ uint32_t SA[4096];
    __shared__ uint32_t SB[4096];

    int tid = threadIdx.x, lane = tid & 31, warp = tid >> 5;
    int wm = warp & 3, wn = warp >> 2;
    int g = lane >> 2, t4 = lane & 3;
    int b = blockIdx.y;
    int m0 = blockIdx.x * 128;
    const float* xb = xT + (size_t)b * 128 * L;

    float acc[2][8][4];
#pragma unroll
    for (int r = 0; r < 2; r++)
#pragma unroll
        for (int nf = 0; nf < 8; nf++)
#pragma unroll
            for (int s = 0; s < 4; s++) acc[r][nf][s] = 0.0f;

    int nch = L >> 5;
    for (int ch = 0; ch < nch; ch++) {
        int k0 = ch << 5;
        __syncthreads();
#pragma unroll
        for (int e = 0; e < 4; e++) {
            int flat = e * 256 + tid;
            int row = flat >> 3, kb = flat & 7;
            float4 av = *(const float4*)(W + (size_t)(m0 + row) * L + k0 + kb * 4);
            stageA4(SA, row, kb, av);
            float4 bv = *(const float4*)(xb + (size_t)row * L + k0 + kb * 4);
            stageB4(SB, row, kb, bv);
        }
        __syncthreads();
#pragma unroll
        for (int ks = 0; ks < 4; ks++) {
            uint32_t a[2][4];
#pragma unroll
            for (int r = 0; r < 2; r++) {
                uint4 t = *(const uint4*)(SA + ((wm * 2 + r) * 4 + ks) * 128 + lane * 4);
                a[r][0] = t.x; a[r][1] = t.y; a[r][2] = t.z; a[r][3] = t.w;
            }
#pragma unroll
            for (int nf = 0; nf < 8; nf++) {
                uint2 bb = *(const uint2*)(SB + ((wn * 8 + nf) * 4 + ks) * 64 + lane * 2);
                mma_tf32(acc[0][nf], a[0], bb.x, bb.y);
                mma_tf32(acc[1][nf], a[1], bb.x, bb.y);
            }
        }
    }

    int TL = 2 * L;
    int cbase = wn * 64 + t4 * 2;
#pragma unroll
    for (int r = 0; r < 2; r++) {
#pragma unroll
        for (int h = 0; h < 2; h++) {
            int mg = b * TL + m0 + wm * 32 + r * 16 + h * 8 + g;
            const float* brow = base + (size_t)mg * 128;
            float* orow = out + (size_t)mg * 128;
#pragma unroll
            for (int nf = 0; nf < 8; nf++) {
                int c = cbase + nf * 8;
                float2 bs = *(const float2*)(brow + c);
                float v0 = fmaf(alpha, acc[r][nf][h * 2 + 0], bs.x);
                float v1 = fmaf(alpha, acc[r][nf][h * 2 + 1], bs.y);
                *(float2*)(orow + c) = make_float2(v0, v1);
            }
        }
    }
}

// ---------------------------------------------------------------------------
extern "C" void kernel_launch(void* const* d_in, const int* in_sizes, int n_in,
                              void* d_out, int out_size) {
    const float* x0 = (const float*)d_in[0];
    const float* x1 = (const float*)d_in[1];
    const float* x2 = (const float*)d_in[2];
    const float* x3 = (const float*)d_in[3];
    const float* c0 = (const float*)d_in[4];
    const float* w0 = (const float*)d_in[5];
    const float* c1 = (const float*)d_in[6];
    const float* w1 = (const float*)d_in[7];
    const float* c2 = (const float*)d_in[8];
    const float* w2 = (const float*)d_in[9];
    const float* c3 = (const float*)d_in[10];
    const float* w3 = (const float*)d_in[11];
    float* out = (float*)d_out;

    float *pW64, *pW128, *pW256, *pCt0, *pCt1, *pCt2, *pCt3, *pbias;
    float *pd1, *pd2, *pd3, *poh1, *poh2, *poh3, *pu, *pxT;
    cudaGetSymbolAddress((void**)&pW64,  g_W64);
    cudaGetSymbolAddress((void**)&pW128, g_W128);
    cudaGetSymbolAddress((void**)&pW256, g_W256);
    cudaGetSymbolAddress((void**)&pCt0,  g_Ct0);
    cudaGetSymbolAddress((void**)&pCt1,  g_Ct1);
    cudaGetSymbolAddress((void**)&pCt2,  g_Ct2);
    cudaGetSymbolAddress((void**)&pCt3,  g_Ct3);
    cudaGetSymbolAddress((void**)&pbias, g_bias);
    cudaGetSymbolAddress((void**)&pd1,   g_d1);
    cudaGetSymbolAddress((void**)&pd2,   g_d2);
    cudaGetSymbolAddress((void**)&pd3,   g_d3);
    cudaGetSymbolAddress((void**)&poh1,  g_oh1);
    cudaGetSymbolAddress((void**)&poh2,  g_oh2);
    cudaGetSymbolAddress((void**)&poh3,  g_oh3);
    cudaGetSymbolAddress((void**)&pu,    g_u);
    cudaGetSymbolAddress((void**)&pxT,   g_xT);

    // setup
    fill_W_kernel<<<(2*64*64   + 255) / 256, 256>>>(pW64,  64);
    fill_W_kernel<<<(2*128*128 + 255) / 256, 256>>>(pW128, 128);
    fill_W_kernel<<<(2*256*256 + 255) / 256, 256>>>(pW256, 256);
    ctT_kernel<<<(128*256 + 255) / 256, 256>>>(c0, pCt0, 2);
    ctT_kernel<<<(128*384 + 255) / 256, 256>>>(c1, pCt1, 3);
    ctT_kernel<<<(128*512 + 255) / 256, 256>>>(c2, pCt2, 4);
    ctT_kernel<<<(128*640 + 255) / 256, 256>>>(c3, pCt3, 5);
    bias_kernel<<<1, 128>>>(c0, pbias + 0 * 128, 2);
    bias_kernel<<<1, 128>>>(c1, pbias + 1 * 128, 3);
    bias_kernel<<<1, 128>>>(c2, pbias + 2 * 128, 4);
    bias_kernel<<<1, 128>>>(c3, pbias + 3 * 128, 5);

    // decomposition: d_k = x_high - interp(x_low)
    { dim3 g(64/32, 4, 128);  transpose_kernel<<<g, dim3(32,8)>>>(x3, pxT, 64); }
    { dim3 g(1, 128);  interp_mma_kernel<<<g, 256>>>(pW64,  pxT, x2, pd1,  64, -1.0f); }
    { dim3 g(128/32, 4, 128); transpose_kernel<<<g, dim3(32,8)>>>(x2, pxT, 128); }
    { dim3 g(2, 128);  interp_mma_kernel<<<g, 256>>>(pW128, pxT, x1, pd2, 128, -1.0f); }
    { dim3 g(256/32, 4, 128); transpose_kernel<<<g, dim3(32,8)>>>(x1, pxT, 256); }
    { dim3 g(4, 128);  interp_mma_kernel<<<g, 256>>>(pW256, pxT, x0, pd3, 256, -1.0f); }

    // m_kan stages
    { int M = 128*64;
      u_kernel<<<(M*128 + 255)/256, 256>>>(x3, pu, M*128);
      mkan_mma_kernel<<<M/128, 256>>>(pu, pCt0, pbias + 0*128, x3, w0, out + OFF64, 256, 64); }
    { int M = 128*128;
      u_kernel<<<(M*128 + 255)/256, 256>>>(pd1, pu, M*128);
      mkan_mma_kernel<<<M/128, 256>>>(pu, pCt1, pbias + 1*128, pd1, w1, poh1, 384, 128); }
    { int M = 128*256;
      u_kernel<<<(M*128 + 255)/256, 256>>>(pd2, pu, M*128);
      mkan_mma_kernel<<<M/128, 256>>>(pu, pCt2, pbias + 2*128, pd2, w2, poh2, 512, 256); }
    { int M = 128*512;
      u_kernel<<<(M*128 + 255)/256, 256>>>(pd3, pu, M*128);
      mkan_mma_kernel<<<M/128, 256>>>(pu, pCt3, pbias + 3*128, pd3, w3, poh3, 640, 512); }

    // mix chain: mix_l = oh_l + interp(mix_{l-1})
    { dim3 g(64/32, 4, 128);  transpose_kernel<<<g, dim3(32,8)>>>(out + OFF64, pxT, 64); }
    { dim3 g(1, 128);  interp_mma_kernel<<<g, 256>>>(pW64,  pxT, poh1, out + OFF128,  64, 1.0f); }
    { dim3 g(128/32, 4, 128); transpose_kernel<<<g, dim3(32,8)>>>(out + OFF128, pxT, 128); }
    { dim3 g(2, 128);  interp_mma_kernel<<<g, 256>>>(pW128, pxT, poh2, out + OFF256, 128, 1.0f); }
    { dim3 g(256/32, 4, 128); transpose_kernel<<<g, dim3(32,8)>>>(out + OFF256, pxT, 256); }
    { dim3 g(4, 128);  interp_mma_kernel<<<g, 256>>>(pW256, pxT, poh3, out + OFF512, 256, 1.0f); }

    (void)in_sizes; (void)n_in; (void)out_size;
}

// round 4
// speedup vs baseline: 3.9218x; 1.4373x over previous
#include <cuda_runtime.h>
#include <math.h>
#include <cstdint>

// ---------------------------------------------------------------------------
// TimeKAN forward, mma.sync tf32, double-buffered smem staging.
// B=128, D=128, LENS={512,256,128,64}, ORDERS={1,2,3,4}.
// freq_interp == batched GEMM with precomputed Dirichlet matrix.
// cheby_kan == GEMM over T_k(tanh(tanh(x))), T_0 folded into bias.
// dw_conv fused into m_kan epilogue. u/transpose fused into GEMM epilogues.
// ---------------------------------------------------------------------------

#define OFF512 0
#define OFF256 8388608
#define OFF128 12582912
#define OFF64  14680064

__device__ float g_W64 [128 *  64];
__device__ float g_W128[256 * 128];
__device__ float g_W256[512 * 256];

__device__ float g_Ct0[128 * 256];
__device__ float g_Ct1[128 * 384];
__device__ float g_Ct2[128 * 512];
__device__ float g_Ct3[128 * 640];
__device__ float g_bias[4 * 128];

__device__ float g_d [128 * 512 * 128];   // dec output, reused per stage
__device__ float g_u [128 * 512 * 128];   // tanh(tanh(d)), reused per stage

__device__ float g_oh1[128 * 128 * 128];
__device__ float g_oh2[128 * 256 * 128];
__device__ float g_oh3[128 * 512 * 128];

__device__ float g_xT [128 * 128 * 512];  // transposed operand scratch A
__device__ float g_xT2[128 * 128 * 256];  // transposed operand scratch B

// smem word strides (padded to avoid STS bank conflicts)
#define ASTR 132
#define BSTR 66
#define A_WORDS (32 * ASTR)   // 32 frags
#define B_WORDS (64 * BSTR)   // 64 frags
// dyn smem layout: SA0, SA1, SB0, SB1, Ws(384), Bsh(128)
#define SMEM_WORDS_GEMM (2 * A_WORDS + 2 * B_WORDS)
#define SMEM_BYTES_INTERP (SMEM_WORDS_GEMM * 4)
#define SMEM_BYTES_MKAN   ((SMEM_WORDS_GEMM + 512) * 4)

// ---------------------------------------------------------------------------
__device__ __forceinline__ uint32_t f2tf32(float f) {
    uint32_t r;
    asm("cvt.rna.tf32.f32 %0, %1;" : "=r"(r) : "f"(f));
    return r;
}
__device__ __forceinline__ void mma_tf32(float c[4], const uint32_t a[4],
                                         uint32_t b0, uint32_t b1) {
    asm volatile(
        "mma.sync.aligned.m16n8k8.row.col.f32.tf32.tf32.f32 "
        "{%0,%1,%2,%3}, {%4,%5,%6,%7}, {%8,%9}, {%0,%1,%2,%3};"
        : "+f"(c[0]), "+f"(c[1]), "+f"(c[2]), "+f"(c[3])
        : "r"(a[0]), "r"(a[1]), "r"(a[2]), "r"(a[3]), "r"(b0), "r"(b1));
}
__device__ __forceinline__ float chebT(int k, float uu) {
    if (k == 1) return uu;
    if (k == 2) return fmaf(2.0f * uu, uu, -1.0f);
    if (k == 3) return uu * fmaf(4.0f * uu, uu, -3.0f);
    float s = uu * uu;
    return fmaf(8.0f * s, s - 1.0f, 1.0f);   // k == 4
}

// fragment-native staging (A: m16k8 frags, B: n8k8 frags)
__device__ __forceinline__ void stageA4(uint32_t* SA, int m, int kb, float4 v) {
    int mf = m >> 4, r = m & 15;
    int kf = kb >> 1;
    int slot = (r >> 3) + ((kb & 1) << 1);
    uint32_t* p = SA + (mf * 4 + kf) * ASTR + (r & 7) * 16 + slot;
    p[0]  = f2tf32(v.x);
    p[4]  = f2tf32(v.y);
    p[8]  = f2tf32(v.z);
    p[12] = f2tf32(v.w);
}
__device__ __forceinline__ void stageB4(uint32_t* SB, int n, int kb, float4 v) {
    int nf = n >> 3;
    int kf = kb >> 1;
    int slot = kb & 1;
    uint32_t* p = SB + (nf * 4 + kf) * BSTR + (n & 7) * 8 + slot;
    p[0] = f2tf32(v.x);
    p[2] = f2tf32(v.y);
    p[4] = f2tf32(v.z);
    p[6] = f2tf32(v.w);
}

// ---------------------------------------------------------------------------
// setup kernels
// ---------------------------------------------------------------------------
__global__ void fill_W_kernel(float* __restrict__ W, int L) {
    int idx = blockIdx.x * blockDim.x + threadIdx.x;
    int total = 2 * L * L;
    if (idx >= total) return;
    int m = idx / L;
    int n = idx - m * L;
    float inv4L = 0.25f / (float)L;
    float val;
    if ((m & 1) == 0) {
        int np = m >> 1;
        val = (((np + n) & 1) ? -inv4L : inv4L);
        if (n == np) val += 0.25f;
    } else {
        int t = m - 2 * n;
        double th = (double)t * M_PI / (2.0 * (double)L);
        double g = sin((double)(L + 1) * th) / sin(th);
        val = (float)(g * 0.25 / (double)L);
    }
    W[idx] = val;
}

// per-o block: CtT[o*Kp + k*128 + i] = coeffs[(i*128+o)*K + k]; bias[o] = sum_i c[i,o,0]
__global__ void prep_kernel(const float* __restrict__ c, float* __restrict__ CtT,
                            float* __restrict__ bias, int K) {
    int o = blockIdx.x;
    int Kp = K * 128;
    for (int cc = threadIdx.x; cc < Kp; cc += blockDim.x) {
        int k = cc >> 7, i = cc & 127;
        CtT[(size_t)o * Kp + cc] = c[(i * 128 + o) * K + k];
    }
    __shared__ float red[256];
    float s = 0.0f;
    for (int i = threadIdx.x; i < 128; i += blockDim.x) s += c[(i * 128 + o) * K];
    red[threadIdx.x] = s;
    __syncthreads();
    for (int st = 128; st > 0; st >>= 1) {
        if (threadIdx.x < st) red[threadIdx.x] += red[threadIdx.x + st];
        __syncthreads();
    }
    if (threadIdx.x == 0) bias[o] = red[0];
}

__global__ void u_kernel(const float* __restrict__ x, float* __restrict__ u, int total) {
    int i = blockIdx.x * blockDim.x + threadIdx.x;
    if (i < total) u[i] = tanhf(tanhf(x[i]));
}

// xT[b,o,n] = x[b,n,o]
__global__ void transpose_kernel(const float* __restrict__ x, float* __restrict__ xT, int L) {
    __shared__ float t[32][33];
    int b = blockIdx.z;
    int n0 = blockIdx.x * 32;
    int o0 = blockIdx.y * 32;
    int tx = threadIdx.x, ty = threadIdx.y;
    const float* xp = x + (size_t)b * L * 128;
    float* xq = xT + (size_t)b * 128 * L;
#pragma unroll
    for (int i = 0; i < 32; i += 8)
        t[ty + i][tx] = xp[(n0 + ty + i) * 128 + o0 + tx];
    __syncthreads();
#pragma unroll
    for (int i = 0; i < 32; i += 8)
        xq[(o0 + ty + i) * L + n0 + tx] = t[tx][ty + i];
}

// ---------------------------------------------------------------------------
// staging helpers for the two GEMMs
// ---------------------------------------------------------------------------
__device__ __forceinline__ void stage_mkan(const float* __restrict__ u,
                                           const float* __restrict__ Bm,
                                           int m0, int Kp, int ch,
                                           uint32_t* SA, uint32_t* SB, int tid) {
    int k0 = ch << 5;
    int kk = ch >> 2;
    int i0 = k0 & 127;
#pragma unroll
    for (int e = 0; e < 4; e++) {
        int flat = e * 256 + tid;
        int row = flat >> 3, kb = flat & 7;
        float4 v = *(const float4*)(u + (size_t)(m0 + row) * 128 + i0 + kb * 4);
        float4 t;
        t.x = chebT(kk, v.x); t.y = chebT(kk, v.y);
        t.z = chebT(kk, v.z); t.w = chebT(kk, v.w);
        stageA4(SA, row, kb, t);
        float4 bv = *(const float4*)(Bm + (size_t)row * Kp + k0 + kb * 4);
        stageB4(SB, row, kb, bv);
    }
}

__device__ __forceinline__ void stage_interp(const float* __restrict__ W,
                                             const float* __restrict__ xb,
                                             int m0, int L, int ch,
                                             uint32_t* SA, uint32_t* SB, int tid) {
    int k0 = ch << 5;
#pragma unroll
    for (int e = 0; e < 4; e++) {
        int flat = e * 256 + tid;
        int row = flat >> 3, kb = flat & 7;
        float4 av = *(const float4*)(W + (size_t)(m0 + row) * L + k0 + kb * 4);
        stageA4(SA, row, kb, av);
        float4 bv = *(const float4*)(xb + (size_t)row * L + k0 + kb * 4);
        stageB4(SB, row, kb, bv);
    }
}

__device__ __forceinline__ void mma_tile(const uint32_t* SA, const uint32_t* SB,
                                         float acc[2][8][4], int wm, int wn, int lane) {
#pragma unroll
    for (int ks = 0; ks < 4; ks++) {
        uint32_t a[2][4];
#pragma unroll
        for (int r = 0; r < 2; r++) {
            uint4 t = *(const uint4*)(SA + ((wm * 2 + r) * 4 + ks) * ASTR + lane * 4);
            a[r][0] = t.x; a[r][1] = t.y; a[r][2] = t.z; a[r][3] = t.w;
        }
#pragma unroll
        for (int nf = 0; nf < 8; nf++) {
            uint2 bb = *(const uint2*)(SB + ((wn * 8 + nf) * 4 + ks) * BSTR + lane * 2);
            mma_tf32(acc[0][nf], a[0], bb.x, bb.y);
            mma_tf32(acc[1][nf], a[1], bb.x, bb.y);
        }
    }
}

// ---------------------------------------------------------------------------
// mkan GEMM: out[m,o] = bias[o] + sum_{kk>=1} T_kk(u[m,:]) . CtT[o,kk,:] + dwconv3(x,w)
// optional xTout: transposed copy of out (for the mix chain).
// ---------------------------------------------------------------------------
__global__ __launch_bounds__(256, 2)
void mkan_mma_kernel(const float* __restrict__ u, const float* __restrict__ Bm,
                     const float* __restrict__ bias, const float* __restrict__ x,
                     const float* __restrict__ w, float* __restrict__ out,
                     int Kp, int Ntime, float* __restrict__ xTout) {
    extern __shared__ uint32_t dynsm[];
    uint32_t* SA0 = dynsm;
    uint32_t* SA1 = SA0 + A_WORDS;
    uint32_t* SB0 = SA1 + A_WORDS;
    uint32_t* SB1 = SB0 + B_WORDS;
    float* Ws  = (float*)(SB1 + B_WORDS);
    float* Bsh = Ws + 384;

    int tid = threadIdx.x, lane = tid & 31, warp = tid >> 5;
    int wm = warp & 3, wn = warp >> 2;
    int g = lane >> 2, t4 = lane & 3;
    int m0 = blockIdx.x * 128;

    for (int j = tid; j < 384; j += 256) Ws[j] = w[j];
    if (tid < 128) Bsh[tid] = bias[tid];

    float acc[2][8][4];
#pragma unroll
    for (int r = 0; r < 2; r++)
#pragma unroll
        for (int nf = 0; nf < 8; nf++)
#pragma unroll
            for (int s = 0; s < 4; s++) acc[r][nf][s] = 0.0f;

    int nch = Kp >> 5;
    const int first = 4;                 // kk=0 folded into bias
    stage_mkan(u, Bm, m0, Kp, first, SA0, SB0, tid);
    __syncthreads();
    for (int ch = first; ch < nch; ch++) {
        int par = (ch - first) & 1;
        uint32_t* SAc = par ? SA1 : SA0;
        uint32_t* SBc = par ? SB1 : SB0;
        if (ch + 1 < nch) {
            uint32_t* SAn = par ? SA0 : SA1;
            uint32_t* SBn = par ? SB0 : SB1;
            stage_mkan(u, Bm, m0, Kp, ch + 1, SAn, SBn, tid);
        }
        mma_tile(SAc, SBc, acc, wm, wn, lane);
        __syncthreads();
    }

    int cbase = wn * 64 + t4 * 2;
#pragma unroll
    for (int r = 0; r < 2; r++) {
#pragma unroll
        for (int h = 0; h < 2; h++) {
            int m = m0 + wm * 32 + r * 16 + h * 8 + g;
            int n = m & (Ntime - 1);
            int bb = m / Ntime;
            const float* xr = x + (size_t)m * 128;
            float* orow = out + (size_t)m * 128;
            bool hasp = n > 0, hasn = n < (Ntime - 1);
#pragma unroll
            for (int nf = 0; nf < 8; nf++) {
                int c = cbase + nf * 8;
                float v0 = acc[r][nf][h * 2 + 0] + Bsh[c];
                float v1 = acc[r][nf][h * 2 + 1] + Bsh[c + 1];
                float2 cur = *(const float2*)(xr + c);
                float2 prv = hasp ? *(const float2*)(xr + c - 128) : make_float2(0.f, 0.f);
                float2 nxt = hasn ? *(const float2*)(xr + c + 128) : make_float2(0.f, 0.f);
                v0 += cur.x * Ws[c * 3 + 1] + prv.x * Ws[c * 3] + nxt.x * Ws[c * 3 + 2];
                v1 += cur.y * Ws[c * 3 + 4] + prv.y * Ws[c * 3 + 3] + nxt.y * Ws[c * 3 + 5];
                *(float2*)(orow + c) = make_float2(v0, v1);
                if (xTout) {
                    xTout[((size_t)bb * 128 + c) * Ntime + n]     = v0;
                    xTout[((size_t)bb * 128 + c + 1) * Ntime + n] = v1;
                }
            }
        }
    }
}

// ---------------------------------------------------------------------------
// interp GEMM: out[b,m,o] = base[b,m,o] + alpha * sum_n W[m,n]*xT[b,o,n]
// optional uout: tanh(tanh(out)); optional xTout: transposed copy of out.
// ---------------------------------------------------------------------------
__global__ __launch_bounds__(256, 2)
void interp_mma_kernel(const float* __restrict__ W, const float* __restrict__ xT,
                       const float* __restrict__ base, float* __restrict__ out,
                       int L, float alpha,
                       float* __restrict__ uout, float* __restrict__ xTout) {
    extern __shared__ uint32_t dynsm[];
    uint32_t* SA0 = dynsm;
    uint32_t* SA1 = SA0 + A_WORDS;
    uint32_t* SB0 = SA1 + A_WORDS;
    uint32_t* SB1 = SB0 + B_WORDS;

    int tid = threadIdx.x, lane = tid & 31, warp = tid >> 5;
    int wm = warp & 3, wn = warp >> 2;
    int g = lane >> 2, t4 = lane & 3;
    int b = blockIdx.y;
    int m0 = blockIdx.x * 128;
    const float* xb = xT + (size_t)b * 128 * L;

    float acc[2][8][4];
#pragma unroll
    for (int r = 0; r < 2; r++)
#pragma unroll
        for (int nf = 0; nf < 8; nf++)
#pragma unroll
            for (int s = 0; s < 4; s++) acc[r][nf][s] = 0.0f;

    int nch = L >> 5;
    stage_interp(W, xb, m0, L, 0, SA0, SB0, tid);
    __syncthreads();
    for (int ch = 0; ch < nch; ch++) {
        int par = ch & 1;
        uint32_t* SAc = par ? SA1 : SA0;
        uint32_t* SBc = par ? SB1 : SB0;
        if (ch + 1 < nch) {
            uint32_t* SAn = par ? SA0 : SA1;
            uint32_t* SBn = par ? SB0 : SB1;
            stage_interp(W, xb, m0, L, ch + 1, SAn, SBn, tid);
        }
        mma_tile(SAc, SBc, acc, wm, wn, lane);
        __syncthreads();
    }

    int TL = 2 * L;
    int cbase = wn * 64 + t4 * 2;
#pragma unroll
    for (int r = 0; r < 2; r++) {
#pragma unroll
        for (int h = 0; h < 2; h++) {
            int ml = m0 + wm * 32 + r * 16 + h * 8 + g;
            int mg = b * TL + ml;
            const float* brow = base + (size_t)mg * 128;
            float* orow = out + (size_t)mg * 128;
#pragma unroll
            for (int nf = 0; nf < 8; nf++) {
                int c = cbase + nf * 8;
                float2 bs = *(const float2*)(brow + c);
                float v0 = fmaf(alpha, acc[r][nf][h * 2 + 0], bs.x);
                float v1 = fmaf(alpha, acc[r][nf][h * 2 + 1], bs.y);
                *(float2*)(orow + c) = make_float2(v0, v1);
                if (uout) {
                    uout[(size_t)mg * 128 + c]     = tanhf(tanhf(v0));
                    uout[(size_t)mg * 128 + c + 1] = tanhf(tanhf(v1));
                }
                if (xTout) {
                    xTout[((size_t)b * 128 + c) * TL + ml]     = v0;
                    xTout[((size_t)b * 128 + c + 1) * TL + ml] = v1;
                }
            }
        }
    }
}

// ---------------------------------------------------------------------------
extern "C" void kernel_launch(void* const* d_in, const int* in_sizes, int n_in,
                              void* d_out, int out_size) {
    const float* x0 = (const float*)d_in[0];
    const float* x1 = (const float*)d_in[1];
    const float* x2 = (const float*)d_in[2];
    const float* x3 = (const float*)d_in[3];
    const float* c0 = (const float*)d_in[4];
    const float* w0 = (const float*)d_in[5];
    const float* c1 = (const float*)d_in[6];
    const float* w1 = (const float*)d_in[7];
    const float* c2 = (const float*)d_in[8];
    const float* w2 = (const float*)d_in[9];
    const float* c3 = (const float*)d_in[10];
    const float* w3 = (const float*)d_in[11];
    float* out = (float*)d_out;

    float *pW64, *pW128, *pW256, *pCt0, *pCt1, *pCt2, *pCt3, *pbias;
    float *pd, *pu, *poh1, *poh2, *poh3, *pxT, *pxT2;
    cudaGetSymbolAddress((void**)&pW64,  g_W64);
    cudaGetSymbolAddress((void**)&pW128, g_W128);
    cudaGetSymbolAddress((void**)&pW256, g_W256);
    cudaGetSymbolAddress((void**)&pCt0,  g_Ct0);
    cudaGetSymbolAddress((void**)&pCt1,  g_Ct1);
    cudaGetSymbolAddress((void**)&pCt2,  g_Ct2);
    cudaGetSymbolAddress((void**)&pCt3,  g_Ct3);
    cudaGetSymbolAddress((void**)&pbias, g_bias);
    cudaGetSymbolAddress((void**)&pd,    g_d);
    cudaGetSymbolAddress((void**)&pu,    g_u);
    cudaGetSymbolAddress((void**)&poh1,  g_oh1);
    cudaGetSymbolAddress((void**)&poh2,  g_oh2);
    cudaGetSymbolAddress((void**)&poh3,  g_oh3);
    cudaGetSymbolAddress((void**)&pxT,   g_xT);
    cudaGetSymbolAddress((void**)&pxT2,  g_xT2);

    cudaFuncSetAttribute(mkan_mma_kernel,
                         cudaFuncAttributeMaxDynamicSharedMemorySize, SMEM_BYTES_MKAN);
    cudaFuncSetAttribute(interp_mma_kernel,
                         cudaFuncAttributeMaxDynamicSharedMemorySize, SMEM_BYTES_INTERP);

    // ---- stage-3 chain first (slot 5 = mkan3 for ncu profiling) ----
    /*0*/ fill_W_kernel<<<(2*256*256 + 255) / 256, 256>>>(pW256, 256);
    /*1*/ { dim3 g(256/32, 4, 128); transpose_kernel<<<g, dim3(32,8)>>>(x1, pxT, 256); }
    /*2*/ { dim3 g(4, 128);
            interp_mma_kernel<<<g, 256, SMEM_BYTES_INTERP>>>(pW256, pxT, x0, pd, 256, -1.0f, pu, nullptr); }
    /*3*/ prep_kernel<<<128, 256>>>(c3, pCt3, pbias + 3*128, 5);
    /*4*/ fill_W_kernel<<<(2*128*128 + 255) / 256, 256>>>(pW128, 128);
    /*5*/ mkan_mma_kernel<<<512, 256, SMEM_BYTES_MKAN>>>(pu, pCt3, pbias + 3*128, pd, w3, poh3, 640, 512, nullptr);

    // ---- stage-2 chain ----
    /*6*/ { dim3 g(128/32, 4, 128); transpose_kernel<<<g, dim3(32,8)>>>(x2, pxT, 128); }
    /*7*/ { dim3 g(2, 128);
            interp_mma_kernel<<<g, 256, SMEM_BYTES_INTERP>>>(pW128, pxT, x1, pd, 128, -1.0f, pu, nullptr); }
    /*8*/ prep_kernel<<<128, 256>>>(c2, pCt2, pbias + 2*128, 4);
    /*9*/ mkan_mma_kernel<<<256, 256, SMEM_BYTES_MKAN>>>(pu, pCt2, pbias + 2*128, pd, w2, poh2, 512, 256, nullptr);

    // ---- stage-1 chain ----
    /*10*/ fill_W_kernel<<<(2*64*64 + 255) / 256, 256>>>(pW64, 64);
    /*11*/ { dim3 g(64/32, 4, 128); transpose_kernel<<<g, dim3(32,8)>>>(x3, pxT, 64); }
    /*12*/ { dim3 g(1, 128);
             interp_mma_kernel<<<g, 256, SMEM_BYTES_INTERP>>>(pW64, pxT, x2, pd, 64, -1.0f, pu, nullptr); }
    /*13*/ prep_kernel<<<128, 256>>>(c1, pCt1, pbias + 1*128, 3);
    /*14*/ mkan_mma_kernel<<<128, 256, SMEM_BYTES_MKAN>>>(pu, pCt1, pbias + 1*128, pd, w1, poh1, 384, 128, nullptr);

    // ---- stage-0 ----
    /*15*/ prep_kernel<<<128, 256>>>(c0, pCt0, pbias + 0*128, 2);
    /*16*/ u_kernel<<<(128*64*128 + 255)/256, 256>>>(x3, pu, 128*64*128);
    /*17*/ mkan_mma_kernel<<<64, 256, SMEM_BYTES_MKAN>>>(pu, pCt0, pbias + 0*128, x3, w0, out + OFF64, 256, 64, pxT2);

    // ---- mix chain: mix_l = oh_l + interp(mix_{l-1}), transposes fused ----
    /*18*/ { dim3 g(1, 128);
             interp_mma_kernel<<<g, 256, SMEM_BYTES_INTERP>>>(pW64,  pxT2, poh1, out + OFF128,  64, 1.0f, nullptr, pxT); }
    /*19*/ { dim3 g(2, 128);
             interp_mma_kernel<<<g, 256, SMEM_BYTES_INTERP>>>(pW128, pxT,  poh2, out + OFF256, 128, 1.0f, nullptr, pxT2); }
    /*20*/ { dim3 g(4, 128);
             interp_mma_kernel<<<g, 256, SMEM_BYTES_INTERP>>>(pW256, pxT2, poh3, out + OFF512, 256, 1.0f, nullptr, nullptr); }

    (void)in_sizes; (void)n_in; (void)out_size;
}

// round 5
// speedup vs baseline: 4.2152x; 1.0748x over previous
#include <cuda_runtime.h>
#include <math.h>
#include <cstdint>

// ---------------------------------------------------------------------------
// TimeKAN forward, mma.sync tf32, batched launches (8 total).
// B=128, D=128, LENS={512,256,128,64}, ORDERS={1,2,3,4}.
// freq_interp == batched GEMM with precomputed Dirichlet matrix.
// cheby_kan == GEMM over T_k(tanh(tanh(x))), T_0 folded into bias.
// dw_conv fused into m_kan epilogue. All MMA operands that are produced by
// our own kernels are stored as tf32 bit patterns (staging = raw copies).
// ---------------------------------------------------------------------------

#define OFF512 0
#define OFF256 8388608
#define OFF128 12582912
#define OFF64  14680064

// W matrices as tf32 bit patterns
__device__ uint32_t g_W64 [128 *  64];
__device__ uint32_t g_W128[256 * 128];
__device__ uint32_t g_W256[512 * 256];

// Ct (K-contiguous coeffs) as tf32 bit patterns, bias fp32
__device__ uint32_t g_Ct0[128 * 256];
__device__ uint32_t g_Ct1[128 * 384];
__device__ uint32_t g_Ct2[128 * 512];
__device__ uint32_t g_Ct3[128 * 640];
__device__ float    g_bias[4 * 128];

// dec outputs d_k (fp32, feed dwconv) and u_k = tanh(tanh(d_k)) (fp32)
__device__ float g_d3[128 * 512 * 128];
__device__ float g_d2[128 * 256 * 128];
__device__ float g_d1[128 * 128 * 128];
__device__ float g_u3[128 * 512 * 128];
__device__ float g_u2[128 * 256 * 128];
__device__ float g_u1[128 * 128 * 128];
__device__ float g_u0[128 *  64 * 128];

// m_kan high-branch outputs (fp32)
__device__ float g_oh1[128 * 128 * 128];
__device__ float g_oh2[128 * 256 * 128];
__device__ float g_oh3[128 * 512 * 128];

// transposed operands (tf32 patterns)
__device__ uint32_t g_xT [128 * 128 * 512];   // holds xT256|xT128|xT64, later reused
__device__ uint32_t g_xT2[128 * 128 * 256];

#define XT256_OFF 0
#define XT128_OFF 4194304
#define XT64_OFF  6291456

// smem strides (padded)
#define ASTR 132
#define BSTR 66
#define A_WORDS (32 * ASTR)
#define B_WORDS (64 * BSTR)
#define SMEM_WORDS_GEMM (2 * A_WORDS + 2 * B_WORDS)
#define SMEM_BYTES_INTERP (SMEM_WORDS_GEMM * 4)
#define SMEM_BYTES_MKAN   ((SMEM_WORDS_GEMM + 512) * 4)

// ---------------------------------------------------------------------------
__device__ __forceinline__ uint32_t f2tf32(float f) {
    uint32_t r;
    asm("cvt.rna.tf32.f32 %0, %1;" : "=r"(r) : "f"(f));
    return r;
}
__device__ __forceinline__ void mma_tf32(float c[4], const uint32_t a[4],
                                         uint32_t b0, uint32_t b1) {
    asm volatile(
        "mma.sync.aligned.m16n8k8.row.col.f32.tf32.tf32.f32 "
        "{%0,%1,%2,%3}, {%4,%5,%6,%7}, {%8,%9}, {%0,%1,%2,%3};"
        : "+f"(c[0]), "+f"(c[1]), "+f"(c[2]), "+f"(c[3])
        : "r"(a[0]), "r"(a[1]), "r"(a[2]), "r"(a[3]), "r"(b0), "r"(b1));
}
__device__ __forceinline__ float chebT(int k, float uu) {
    if (k == 1) return uu;
    if (k == 2) return fmaf(2.0f * uu, uu, -1.0f);
    if (k == 3) return uu * fmaf(4.0f * uu, uu, -3.0f);
    float s = uu * uu;
    return fmaf(8.0f * s, s - 1.0f, 1.0f);   // k == 4
}

// fragment-native staging
__device__ __forceinline__ void stageA4u(uint32_t* SA, int m, int kb, uint4 v) {
    int mf = m >> 4, r = m & 15;
    int kf = kb >> 1;
    int slot = (r >> 3) + ((kb & 1) << 1);
    uint32_t* p = SA + (mf * 4 + kf) * ASTR + (r & 7) * 16 + slot;
    p[0] = v.x; p[4] = v.y; p[8] = v.z; p[12] = v.w;
}
__device__ __forceinline__ void stageA4f(uint32_t* SA, int m, int kb, float4 v) {
    uint4 t;
    t.x = f2tf32(v.x); t.y = f2tf32(v.y); t.z = f2tf32(v.z); t.w = f2tf32(v.w);
    stageA4u(SA, m, kb, t);
}
__device__ __forceinline__ void stageB4u(uint32_t* SB, int n, int kb, uint4 v) {
    int nf = n >> 3;
    int kf = kb >> 1;
    int slot = kb & 1;
    uint32_t* p = SB + (nf * 4 + kf) * BSTR + (n & 7) * 8 + slot;
    p[0] = v.x; p[2] = v.y; p[4] = v.z; p[6] = v.w;
}

__device__ __forceinline__ void mma_tile(const uint32_t* SA, const uint32_t* SB,
                                         float acc[2][8][4], int wm, int wn, int lane) {
#pragma unroll
    for (int ks = 0; ks < 4; ks++) {
        uint32_t a[2][4];
#pragma unroll
        for (int r = 0; r < 2; r++) {
            uint4 t = *(const uint4*)(SA + ((wm * 2 + r) * 4 + ks) * ASTR + lane * 4);
            a[r][0] = t.x; a[r][1] = t.y; a[r][2] = t.z; a[r][3] = t.w;
        }
#pragma unroll
        for (int nf = 0; nf < 8; nf++) {
            uint2 bb = *(const uint2*)(SB + ((wn * 8 + nf) * 4 + ks) * BSTR + lane * 2);
            mma_tf32(acc[0][nf], a[0], bb.x, bb.y);
            mma_tf32(acc[1][nf], a[1], bb.x, bb.y);
        }
    }
}

__device__ __forceinline__ void stage_interp(const uint32_t* __restrict__ W,
                                             const uint32_t* __restrict__ xb,
                                             int m0, int L, int ch,
                                             uint32_t* SA, uint32_t* SB, int tid) {
    int k0 = ch << 5;
#pragma unroll
    for (int e = 0; e < 4; e++) {
        int flat = e * 256 + tid;
        int row = flat >> 3, kb = flat & 7;
        uint4 av = *(const uint4*)(W + (size_t)(m0 + row) * L + k0 + kb * 4);
        stageA4u(SA, row, kb, av);
        uint4 bv = *(const uint4*)(xb + (size_t)row * L + k0 + kb * 4);
        stageB4u(SB, row, kb, bv);
    }
}
__device__ __forceinline__ void stage_mkan(const float* __restrict__ u,
                                           const uint32_t* __restrict__ Bm,
                                           int m0, int Kp, int ch,
                                           uint32_t* SA, uint32_t* SB, int tid) {
    int k0 = ch << 5;
    int kk = ch >> 2;
    int i0 = k0 & 127;
#pragma unroll
    for (int e = 0; e < 4; e++) {
        int flat = e * 256 + tid;
        int row = flat >> 3, kb = flat & 7;
        float4 v = *(const float4*)(u + (size_t)(m0 + row) * 128 + i0 + kb * 4);
        float4 t;
        t.x = chebT(kk, v.x); t.y = chebT(kk, v.y);
        t.z = chebT(kk, v.z); t.w = chebT(kk, v.w);
        stageA4f(SA, row, kb, t);
        uint4 bv = *(const uint4*)(Bm + (size_t)row * Kp + k0 + kb * 4);
        stageB4u(SB, row, kb, bv);
    }
}

// ---------------------------------------------------------------------------
// setup kernels (batched)
// ---------------------------------------------------------------------------
__device__ __forceinline__ float w_val(int m, int n, int L) {
    float inv4L = 0.25f / (float)L;
    if ((m & 1) == 0) {
        int np = m >> 1;
        float v = (((np + n) & 1) ? -inv4L : inv4L);
        if (n == np) v += 0.25f;
        return v;
    }
    int t = m - 2 * n;
    double th = (double)t * M_PI / (2.0 * (double)L);
    double g = sin((double)(L + 1) * th) / sin(th);
    return (float)(g * 0.25 / (double)L);
}

__global__ void fill_all_kernel(uint32_t* __restrict__ W256,
                                uint32_t* __restrict__ W128,
                                uint32_t* __restrict__ W64) {
    int idx = blockIdx.x * blockDim.x + threadIdx.x;
    if (idx < 131072) {
        int m = idx >> 8, n = idx & 255;
        W256[idx] = f2tf32(w_val(m, n, 256));
    } else if (idx < 163840) {
        int j = idx - 131072;
        int m = j >> 7, n = j & 127;
        W128[j] = f2tf32(w_val(m, n, 128));
    } else if (idx < 172032) {
        int j = idx - 163840;
        int m = j >> 6, n = j & 63;
        W64[j] = f2tf32(w_val(m, n, 64));
    }
}

struct PP { const float* c; uint32_t* Ct; float* bias; int K; };
__global__ void prep_all_kernel(PP p0, PP p1, PP p2, PP p3) {
    int stage = blockIdx.x >> 7;
    int o = blockIdx.x & 127;
    PP p = (stage == 0) ? p0 : (stage == 1) ? p1 : (stage == 2) ? p2 : p3;
    int Kp = p.K * 128;
    for (int cc = threadIdx.x; cc < Kp; cc += blockDim.x) {
        int k = cc >> 7, i = cc & 127;
        p.Ct[(size_t)o * Kp + cc] = f2tf32(p.c[(i * 128 + o) * p.K + k]);
    }
    __shared__ float red[256];
    float s = 0.0f;
    for (int i = threadIdx.x; i < 128; i += blockDim.x) s += p.c[(i * 128 + o) * p.K];
    red[threadIdx.x] = s;
    __syncthreads();
    for (int st = 128; st > 0; st >>= 1) {
        if (threadIdx.x < st) red[threadIdx.x] += red[threadIdx.x + st];
        __syncthreads();
    }
    if (threadIdx.x == 0) p.bias[o] = red[0];
}

// batched transpose: xT[b,o,n] = tf32(x[b,n,o])
__global__ void transpose_all_kernel(const float* __restrict__ x1,
                                     const float* __restrict__ x2,
                                     const float* __restrict__ x3,
                                     uint32_t* __restrict__ xT) {
    __shared__ float t[32][33];
    int bx = blockIdx.x;
    const float* xp;
    uint32_t* xq;
    int L, tidx;
    if (bx < 32)      { L = 256; xp = x1; xq = xT + XT256_OFF; tidx = bx; }
    else if (bx < 48) { L = 128; xp = x2; xq = xT + XT128_OFF; tidx = bx - 32; }
    else              { L = 64;  xp = x3; xq = xT + XT64_OFF;  tidx = bx - 48; }
    int ntiles = L >> 5;
    int n0 = (tidx % ntiles) * 32;
    int o0 = (tidx / ntiles) * 32;
    int b = blockIdx.z;
    int tx = threadIdx.x, ty = threadIdx.y;
    xp += (size_t)b * L * 128;
    xq += (size_t)b * 128 * L;
#pragma unroll
    for (int i = 0; i < 32; i += 8)
        t[ty + i][tx] = xp[(n0 + ty + i) * 128 + o0 + tx];
    __syncthreads();
#pragma unroll
    for (int i = 0; i < 32; i += 8)
        xq[(o0 + ty + i) * L + n0 + tx] = f2tf32(t[tx][ty + i]);
}

// ---------------------------------------------------------------------------
// batched dec interp: d = base - W @ xT (per batch), u = tanh(tanh(d)),
// plus a tail region computing u0 = tanh(tanh(x3)).
// ---------------------------------------------------------------------------
struct IP { const uint32_t* W; const uint32_t* xT; const float* base;
            float* d; float* u; int L; };

__global__ __launch_bounds__(256, 2)
void dec_batched_kernel(IP p3, IP p2, IP p1,
                        const float* __restrict__ x3src, float* __restrict__ u0out) {
    int bx = blockIdx.x;
    int tid = threadIdx.x;
    IP p;
    int mblk, b;
    if (bx < 512)      { p = p3; mblk = bx & 3;          b = bx >> 2; }
    else if (bx < 768) { p = p2; mblk = (bx - 512) & 1;  b = (bx - 512) >> 1; }
    else if (bx < 896) { p = p1; mblk = 0;               b = bx - 768; }
    else {
        // u0 tail: 64 blocks x 256 threads x 16 float4
        int r = bx - 896;
        const float4* s = (const float4*)x3src;
        float4* dst = (float4*)u0out;
#pragma unroll
        for (int j = 0; j < 16; j++) {
            int id = r * 4096 + j * 256 + tid;
            float4 v = s[id];
            v.x = tanhf(tanhf(v.x)); v.y = tanhf(tanhf(v.y));
            v.z = tanhf(tanhf(v.z)); v.w = tanhf(tanhf(v.w));
            dst[id] = v;
        }
        return;
    }

    extern __shared__ uint32_t dynsm[];
    uint32_t* SA0 = dynsm;
    uint32_t* SA1 = SA0 + A_WORDS;
    uint32_t* SB0 = SA1 + A_WORDS;
    uint32_t* SB1 = SB0 + B_WORDS;

    int lane = tid & 31, warp = tid >> 5;
    int wm = warp & 3, wn = warp >> 2;
    int g = lane >> 2, t4 = lane & 3;
    int L = p.L;
    int m0 = mblk * 128;
    const uint32_t* xb = p.xT + (size_t)b * 128 * L;

    float acc[2][8][4];
#pragma unroll
    for (int r = 0; r < 2; r++)
#pragma unroll
        for (int nf = 0; nf < 8; nf++)
#pragma unroll
            for (int s = 0; s < 4; s++) acc[r][nf][s] = 0.0f;

    int nch = L >> 5;
    stage_interp(p.W, xb, m0, L, 0, SA0, SB0, tid);
    __syncthreads();
    for (int ch = 0; ch < nch; ch++) {
        int par = ch & 1;
        uint32_t* SAc = par ? SA1 : SA0;
        uint32_t* SBc = par ? SB1 : SB0;
        if (ch + 1 < nch)
            stage_interp(p.W, xb, m0, L, ch + 1, par ? SA0 : SA1, par ? SB0 : SB1, tid);
        mma_tile(SAc, SBc, acc, wm, wn, lane);
        __syncthreads();
    }

    int TL = 2 * L;
    int cbase = wn * 64 + t4 * 2;
#pragma unroll
    for (int r = 0; r < 2; r++) {
#pragma unroll
        for (int h = 0; h < 2; h++) {
            int ml = m0 + wm * 32 + r * 16 + h * 8 + g;
            int mg = b * TL + ml;
            const float* brow = p.base + (size_t)mg * 128;
            float* drow = p.d + (size_t)mg * 128;
            float* urow = p.u + (size_t)mg * 128;
#pragma unroll
            for (int nf = 0; nf < 8; nf++) {
                int c = cbase + nf * 8;
                float2 bs = *(const float2*)(brow + c);
                float v0 = bs.x - acc[r][nf][h * 2 + 0];
                float v1 = bs.y - acc[r][nf][h * 2 + 1];
                *(float2*)(drow + c) = make_float2(v0, v1);
                urow[c]     = tanhf(tanhf(v0));
                urow[c + 1] = tanhf(tanhf(v1));
            }
        }
    }
}

// ---------------------------------------------------------------------------
// batched mkan: out = bias + cheby GEMM + dwconv3(x, w); optional xTout (tf32)
// ---------------------------------------------------------------------------
struct MP { const float* u; const uint32_t* Bm; const float* bias;
            const float* x; const float* w; float* out;
            uint32_t* xTout; int Kp; int Ntime; };

__global__ __launch_bounds__(256, 2)
void mkan_batched_kernel(MP s3, MP s2, MP s1, MP s0) {
    int bx = blockIdx.x;
    MP p;
    int m0;
    if (bx < 512)      { p = s3; m0 = bx * 128; }
    else if (bx < 768) { p = s2; m0 = (bx - 512) * 128; }
    else if (bx < 896) { p = s1; m0 = (bx - 768) * 128; }
    else               { p = s0; m0 = (bx - 896) * 128; }

    extern __shared__ uint32_t dynsm[];
    uint32_t* SA0 = dynsm;
    uint32_t* SA1 = SA0 + A_WORDS;
    uint32_t* SB0 = SA1 + A_WORDS;
    uint32_t* SB1 = SB0 + B_WORDS;
    float* Ws  = (float*)(SB1 + B_WORDS);
    float* Bsh = Ws + 384;

    int tid = threadIdx.x, lane = tid & 31, warp = tid >> 5;
    int wm = warp & 3, wn = warp >> 2;
    int g = lane >> 2, t4 = lane & 3;

    for (int j = tid; j < 384; j += 256) Ws[j] = p.w[j];
    if (tid < 128) Bsh[tid] = p.bias[tid];

    float acc[2][8][4];
#pragma unroll
    for (int r = 0; r < 2; r++)
#pragma unroll
        for (int nf = 0; nf < 8; nf++)
#pragma unroll
            for (int s = 0; s < 4; s++) acc[r][nf][s] = 0.0f;

    int nch = p.Kp >> 5;
    const int first = 4;               // kk = 0 folded into bias
    stage_mkan(p.u, p.Bm, m0, p.Kp, first, SA0, SB0, tid);
    __syncthreads();
    for (int ch = first; ch < nch; ch++) {
        int par = (ch - first) & 1;
        uint32_t* SAc = par ? SA1 : SA0;
        uint32_t* SBc = par ? SB1 : SB0;
        if (ch + 1 < nch)
            stage_mkan(p.u, p.Bm, m0, p.Kp, ch + 1, par ? SA0 : SA1, par ? SB0 : SB1, tid);
        mma_tile(SAc, SBc, acc, wm, wn, lane);
        __syncthreads();
    }

    int Ntime = p.Ntime;
    int cbase = wn * 64 + t4 * 2;
#pragma unroll
    for (int r = 0; r < 2; r++) {
#pragma unroll
        for (int h = 0; h < 2; h++) {
            int m = m0 + wm * 32 + r * 16 + h * 8 + g;
            int n = m & (Ntime - 1);
            int bb = m / Ntime;
            const float* xr = p.x + (size_t)m * 128;
            float* orow = p.out + (size_t)m * 128;
            bool hasp = n > 0, hasn = n < (Ntime - 1);
#pragma unroll
            for (int nf = 0; nf < 8; nf++) {
                int c = cbase + nf * 8;
                float v0 = acc[r][nf][h * 2 + 0] + Bsh[c];
                float v1 = acc[r][nf][h * 2 + 1] + Bsh[c + 1];
                float2 cur = *(const float2*)(xr + c);
                float2 prv = hasp ? *(const float2*)(xr + c - 128) : make_float2(0.f, 0.f);
                float2 nxt = hasn ? *(const float2*)(xr + c + 128) : make_float2(0.f, 0.f);
                v0 += cur.x * Ws[c * 3 + 1] + prv.x * Ws[c * 3] + nxt.x * Ws[c * 3 + 2];
                v1 += cur.y * Ws[c * 3 + 4] + prv.y * Ws[c * 3 + 3] + nxt.y * Ws[c * 3 + 5];
                *(float2*)(orow + c) = make_float2(v0, v1);
                if (p.xTout) {
                    p.xTout[((size_t)bb * 128 + c) * Ntime + n]     = f2tf32(v0);
                    p.xTout[((size_t)bb * 128 + c + 1) * Ntime + n] = f2tf32(v1);
                }
            }
        }
    }
}

// ---------------------------------------------------------------------------
// mix interp: out[b,m,o] = base[b,m,o] + sum_n W[m,n]*xT[b,o,n], opt xTout
// ---------------------------------------------------------------------------
__global__ __launch_bounds__(256, 2)
void interp_mma_kernel(const uint32_t* __restrict__ W, const uint32_t* __restrict__ xT,
                       const float* __restrict__ base, float* __restrict__ out,
                       int L, uint32_t* __restrict__ xTout) {
    extern __shared__ uint32_t dynsm[];
    uint32_t* SA0 = dynsm;
    uint32_t* SA1 = SA0 + A_WORDS;
    uint32_t* SB0 = SA1 + A_WORDS;
    uint32_t* SB1 = SB0 + B_WORDS;

    int tid = threadIdx.x, lane = tid & 31, warp = tid >> 5;
    int wm = warp & 3, wn = warp >> 2;
    int g = lane >> 2, t4 = lane & 3;
    int b = blockIdx.y;
    int m0 = blockIdx.x * 128;
    const uint32_t* xb = xT + (size_t)b * 128 * L;

    float acc[2][8][4];
#pragma unroll
    for (int r = 0; r < 2; r++)
#pragma unroll
        for (int nf = 0; nf < 8; nf++)
#pragma unroll
            for (int s = 0; s < 4; s++) acc[r][nf][s] = 0.0f;

    int nch = L >> 5;
    stage_interp(W, xb, m0, L, 0, SA0, SB0, tid);
    __syncthreads();
    for (int ch = 0; ch < nch; ch++) {
        int par = ch & 1;
        uint32_t* SAc = par ? SA1 : SA0;
        uint32_t* SBc = par ? SB1 : SB0;
        if (ch + 1 < nch)
            stage_interp(W, xb, m0, L, ch + 1, par ? SA0 : SA1, par ? SB0 : SB1, tid);
        mma_tile(SAc, SBc, acc, wm, wn, lane);
        __syncthreads();
    }

    int TL = 2 * L;
    int cbase = wn * 64 + t4 * 2;
#pragma unroll
    for (int r = 0; r < 2; r++) {
#pragma unroll
        for (int h = 0; h < 2; h++) {
            int ml = m0 + wm * 32 + r * 16 + h * 8 + g;
            int mg = b * TL + ml;
            const float* brow = base + (size_t)mg * 128;
            float* orow = out + (size_t)mg * 128;
#pragma unroll
            for (int nf = 0; nf < 8; nf++) {
                int c = cbase + nf * 8;
                float2 bs = *(const float2*)(brow + c);
                float v0 = acc[r][nf][h * 2 + 0] + bs.x;
                float v1 = acc[r][nf][h * 2 + 1] + bs.y;
                *(float2*)(orow + c) = make_float2(v0, v1);
                if (xTout) {
                    xTout[((size_t)b * 128 + c) * TL + ml]     = f2tf32(v0);
                    xTout[((size_t)b * 128 + c + 1) * TL + ml] = f2tf32(v1);
                }
            }
        }
    }
}

// ---------------------------------------------------------------------------
extern "C" void kernel_launch(void* const* d_in, const int* in_sizes, int n_in,
                              void* d_out, int out_size) {
    const float* x0 = (const float*)d_in[0];
    const float* x1 = (const float*)d_in[1];
    const float* x2 = (const float*)d_in[2];
    const float* x3 = (const float*)d_in[3];
    const float* c0 = (const float*)d_in[4];
    const float* w0 = (const float*)d_in[5];
    const float* c1 = (const float*)d_in[6];
    const float* w1 = (const float*)d_in[7];
    const float* c2 = (const float*)d_in[8];
    const float* w2 = (const float*)d_in[9];
    const float* c3 = (const float*)d_in[10];
    const float* w3 = (const float*)d_in[11];
    float* out = (float*)d_out;

    uint32_t *pW64, *pW128, *pW256, *pCt0, *pCt1, *pCt2, *pCt3, *pxT, *pxT2;
    float *pbias, *pd3, *pd2, *pd1, *pu3, *pu2, *pu1, *pu0, *poh1, *poh2, *poh3;
    cudaGetSymbolAddress((void**)&pW64,  g_W64);
    cudaGetSymbolAddress((void**)&pW128, g_W128);
    cudaGetSymbolAddress((void**)&pW256, g_W256);
    cudaGetSymbolAddress((void**)&pCt0,  g_Ct0);
    cudaGetSymbolAddress((void**)&pCt1,  g_Ct1);
    cudaGetSymbolAddress((void**)&pCt2,  g_Ct2);
    cudaGetSymbolAddress((void**)&pCt3,  g_Ct3);
    cudaGetSymbolAddress((void**)&pbias, g_bias);
    cudaGetSymbolAddress((void**)&pd3,   g_d3);
    cudaGetSymbolAddress((void**)&pd2,   g_d2);
    cudaGetSymbolAddress((void**)&pd1,   g_d1);
    cudaGetSymbolAddress((void**)&pu3,   g_u3);
    cudaGetSymbolAddress((void**)&pu2,   g_u2);
    cudaGetSymbolAddress((void**)&pu1,   g_u1);
    cudaGetSymbolAddress((void**)&pu0,   g_u0);
    cudaGetSymbolAddress((void**)&poh1,  g_oh1);
    cudaGetSymbolAddress((void**)&poh2,  g_oh2);
    cudaGetSymbolAddress((void**)&poh3,  g_oh3);
    cudaGetSymbolAddress((void**)&pxT,   g_xT);
    cudaGetSymbolAddress((void**)&pxT2,  g_xT2);

    cudaFuncSetAttribute(dec_batched_kernel,
                         cudaFuncAttributeMaxDynamicSharedMemorySize, SMEM_BYTES_INTERP);
    cudaFuncSetAttribute(mkan_batched_kernel,
                         cudaFuncAttributeMaxDynamicSharedMemorySize, SMEM_BYTES_MKAN);
    cudaFuncSetAttribute(interp_mma_kernel,
                         cudaFuncAttributeMaxDynamicSharedMemorySize, SMEM_BYTES_INTERP);

    /*0*/ fill_all_kernel<<<(172032 + 255) / 256, 256>>>(pW256, pW128, pW64);
    /*1*/ {
        PP p0 = {c0, pCt0, pbias + 0 * 128, 2};
        PP p1 = {c1, pCt1, pbias + 1 * 128, 3};
        PP p2 = {c2, pCt2, pbias + 2 * 128, 4};
        PP p3 = {c3, pCt3, pbias + 3 * 128, 5};
        prep_all_kernel<<<512, 256>>>(p0, p1, p2, p3);
    }
    /*2*/ transpose_all_kernel<<<dim3(56, 1, 128), dim3(32, 8)>>>(x1, x2, x3, pxT);
    /*3*/ {
        IP p3s = {pW256, pxT + XT256_OFF, x0, pd3, pu3, 256};
        IP p2s = {pW128, pxT + XT128_OFF, x1, pd2, pu2, 128};
        IP p1s = {pW64,  pxT + XT64_OFF,  x2, pd1, pu1, 64};
        dec_batched_kernel<<<960, 256, SMEM_BYTES_INTERP>>>(p3s, p2s, p1s, x3, pu0);
    }
    /*4*/ {
        MP s3 = {pu3, pCt3, pbias + 3 * 128, pd3, w3, poh3, nullptr, 640, 512};
        MP s2 = {pu2, pCt2, pbias + 2 * 128, pd2, w2, poh2, nullptr, 512, 256};
        MP s1 = {pu1, pCt1, pbias + 1 * 128, pd1, w1, poh1, nullptr, 384, 128};
        MP s0 = {pu0, pCt0, pbias + 0 * 128, x3, w0, out + OFF64, pxT2, 256, 64};
        mkan_batched_kernel<<<960, 256, SMEM_BYTES_MKAN>>>(s3, s2, s1, s0);
    }
    // mix chain (sequential by data dependency)
    /*5*/ { dim3 g(1, 128);
            interp_mma_kernel<<<g, 256, SMEM_BYTES_INTERP>>>(pW64,  pxT2, poh1, out + OFF128,  64, pxT); }
    /*6*/ { dim3 g(2, 128);
            interp_mma_kernel<<<g, 256, SMEM_BYTES_INTERP>>>(pW128, pxT,  poh2, out + OFF256, 128, pxT2); }
    /*7*/ { dim3 g(4, 128);
            interp_mma_kernel<<<g, 256, SMEM_BYTES_INTERP>>>(pW256, pxT2, poh3, out + OFF512, 256, nullptr); }

    (void)in_sizes; (void)n_in; (void)out_size;
}

// round 6
// speedup vs baseline: 4.3910x; 1.0417x over previous
#include <cuda_runtime.h>
#include <math.h>
#include <cstdint>

// ---------------------------------------------------------------------------
// TimeKAN forward, mma.sync tf32, batched launches, wide-store staging.
// B=128, D=128, LENS={512,256,128,64}, ORDERS={1,2,3,4}.
// ---------------------------------------------------------------------------

#define OFF512 0
#define OFF256 8388608
#define OFF128 12582912
#define OFF64  14680064

__device__ uint32_t g_W64 [128 *  64];
__device__ uint32_t g_W128[256 * 128];
__device__ uint32_t g_W256[512 * 256];

__device__ uint32_t g_Ct0[128 * 256];
__device__ uint32_t g_Ct1[128 * 384];
__device__ uint32_t g_Ct2[128 * 512];
__device__ uint32_t g_Ct3[128 * 640];
__device__ float    g_bias[4 * 128];

__device__ float g_d3[128 * 512 * 128];
__device__ float g_d2[128 * 256 * 128];
__device__ float g_d1[128 * 128 * 128];
__device__ float g_u3[128 * 512 * 128];
__device__ float g_u2[128 * 256 * 128];
__device__ float g_u1[128 * 128 * 128];
__device__ float g_u0[128 *  64 * 128];

__device__ float g_oh1[128 * 128 * 128];
__device__ float g_oh2[128 * 256 * 128];
__device__ float g_oh3[128 * 512 * 128];

__device__ uint32_t g_xT [128 * 128 * 512];
__device__ uint32_t g_xT2[128 * 128 * 256];

#define XT256_OFF 0
#define XT128_OFF 4194304
#define XT64_OFF  6291456

// smem strides in words: both ≡ 4 (mod 32) for conflict-free STS.128 staging
#define ASTR 132
#define BSTR 68
#define A_WORDS (32 * ASTR)    // 4224
#define B_WORDS (64 * BSTR)    // 4352
#define SMEM_WORDS_GEMM (2 * A_WORDS + 2 * B_WORDS)
#define SMEM_BYTES_INTERP (SMEM_WORDS_GEMM * 4)
#define SMEM_BYTES_MKAN   ((SMEM_WORDS_GEMM + 512) * 4)

// ---------------------------------------------------------------------------
__device__ __forceinline__ uint32_t f2tf32(float f) {
    uint32_t r;
    asm("cvt.rna.tf32.f32 %0, %1;" : "=r"(r) : "f"(f));
    return r;
}
__device__ __forceinline__ void mma_tf32(float c[4], const uint32_t a[4],
                                         uint32_t b0, uint32_t b1) {
    asm volatile(
        "mma.sync.aligned.m16n8k8.row.col.f32.tf32.tf32.f32 "
        "{%0,%1,%2,%3}, {%4,%5,%6,%7}, {%8,%9}, {%0,%1,%2,%3};"
        : "+f"(c[0]), "+f"(c[1]), "+f"(c[2]), "+f"(c[3])
        : "r"(a[0]), "r"(a[1]), "r"(a[2]), "r"(a[3]), "r"(b0), "r"(b1));
}
__device__ __forceinline__ float chebT(int k, float uu) {
    if (k == 1) return uu;
    if (k == 2) return fmaf(2.0f * uu, uu, -1.0f);
    if (k == 3) return uu * fmaf(4.0f * uu, uu, -3.0f);
    float s = uu * uu;
    return fmaf(8.0f * s, s - 1.0f, 1.0f);   // k == 4
}

// ---------------------------------------------------------------------------
// Wide staging.
// A frag layout word: frag*ASTR + lane*4 + slot; lane=(m&7)*4+(k&3),
// slot=((m>>3)&1)+2*((k>>2)&1).  Thread (kf=tid&3, m7=(tid>>2)&7, mf=tid>>5)
// owns the 16 words [ (mf*4+kf)*ASTR + m7*16 .. +15 ]  -> 4 STS.128.
// B frag layout word: frag*BSTR + lane*2 + slot; lane=(n&7)*4+(k&3),
// slot=(k>>2)&1.  Thread unit (kf, nf, n7) owns 8 words -> 2 STS.128.
// ---------------------------------------------------------------------------
__device__ __forceinline__ void storeA16(uint32_t* SA, int mf, int kf, int m7,
                                         uint4 v0, uint4 v1, uint4 v2, uint4 v3) {
    // v0 = row m,  k0..k0+3 ; v1 = row m,  k0+4..+7
    // v2 = row m+8,k0..k0+3 ; v3 = row m+8,k0+4..+7
    uint4* p = (uint4*)(SA + (mf * 4 + kf) * ASTR + m7 * 16);
    p[0] = make_uint4(v0.x, v2.x, v1.x, v3.x);
    p[1] = make_uint4(v0.y, v2.y, v1.y, v3.y);
    p[2] = make_uint4(v0.z, v2.z, v1.z, v3.z);
    p[3] = make_uint4(v0.w, v2.w, v1.w, v3.w);
}
__device__ __forceinline__ void storeB8(uint32_t* SB, int nf, int kf, int n7,
                                        uint4 v0, uint4 v1) {
    uint4* p = (uint4*)(SB + (nf * 4 + kf) * BSTR + n7 * 8);
    p[0] = make_uint4(v0.x, v1.x, v0.y, v1.y);
    p[1] = make_uint4(v0.z, v1.z, v0.w, v1.w);
}

__device__ __forceinline__ void stage_interp(const uint32_t* __restrict__ W,
                                             const uint32_t* __restrict__ xb,
                                             int m0, int L, int ch,
                                             uint32_t* SA, uint32_t* SB, int tid) {
    int k0 = ch << 5;
    {   // A: W rows m0+mf*16+m7 (+8), k0+kf*8 .. +7
        int kf = tid & 3, m7 = (tid >> 2) & 7, mf = tid >> 5;
        const uint32_t* r0 = W + (size_t)(m0 + mf * 16 + m7) * L + k0 + kf * 8;
        const uint32_t* r1 = r0 + (size_t)8 * L;
        uint4 v0 = *(const uint4*)r0;
        uint4 v1 = *(const uint4*)(r0 + 4);
        uint4 v2 = *(const uint4*)r1;
        uint4 v3 = *(const uint4*)(r1 + 4);
        storeA16(SA, mf, kf, m7, v0, v1, v2, v3);
    }
    {   // B: xb rows nf*8+n7, two units nf and nf+8
        int kf = tid & 3, nfl = (tid >> 2) & 1, n7 = (tid >> 3) & 7, nfh = tid >> 6;
#pragma unroll
        for (int uu = 0; uu < 2; uu++) {
            int nf = nfh * 2 + nfl + uu * 8;
            const uint32_t* rn = xb + (size_t)(nf * 8 + n7) * L + k0 + kf * 8;
            uint4 v0 = *(const uint4*)rn;
            uint4 v1 = *(const uint4*)(rn + 4);
            storeB8(SB, nf, kf, n7, v0, v1);
        }
    }
}

__device__ __forceinline__ void stage_mkan(const float* __restrict__ u,
                                           const uint32_t* __restrict__ Bm,
                                           int m0, int Kp, int ch,
                                           uint32_t* SA, uint32_t* SB, int tid) {
    int k0 = ch << 5;
    {   // A: chebT(kk, u) on the fly
        int kf = tid & 3, m7 = (tid >> 2) & 7, mf = tid >> 5;
        int kk = ch >> 2;
        int i0 = ((ch & 3) << 5) + kf * 8;
        const float* r0 = u + (size_t)(m0 + mf * 16 + m7) * 128 + i0;
        const float* r1 = r0 + 8 * 128;
        float4 f0 = *(const float4*)r0;
        float4 f1 = *(const float4*)(r0 + 4);
        float4 f2 = *(const float4*)r1;
        float4 f3 = *(const float4*)(r1 + 4);
        uint4 v0, v1, v2, v3;
        v0.x = f2tf32(chebT(kk, f0.x)); v0.y = f2tf32(chebT(kk, f0.y));
        v0.z = f2tf32(chebT(kk, f0.z)); v0.w = f2tf32(chebT(kk, f0.w));
        v1.x = f2tf32(chebT(kk, f1.x)); v1.y = f2tf32(chebT(kk, f1.y));
        v1.z = f2tf32(chebT(kk, f1.z)); v1.w = f2tf32(chebT(kk, f1.w));
        v2.x = f2tf32(chebT(kk, f2.x)); v2.y = f2tf32(chebT(kk, f2.y));
        v2.z = f2tf32(chebT(kk, f2.z)); v2.w = f2tf32(chebT(kk, f2.w));
        v3.x = f2tf32(chebT(kk, f3.x)); v3.y = f2tf32(chebT(kk, f3.y));
        v3.z = f2tf32(chebT(kk, f3.z)); v3.w = f2tf32(chebT(kk, f3.w));
        storeA16(SA, mf, kf, m7, v0, v1, v2, v3);
    }
    {   // B: Ct rows
        int kf = tid & 3, nfl = (tid >> 2) & 1, n7 = (tid >> 3) & 7, nfh = tid >> 6;
#pragma unroll
        for (int uu = 0; uu < 2; uu++) {
            int nf = nfh * 2 + nfl + uu * 8;
            const uint32_t* rn = Bm + (size_t)(nf * 8 + n7) * Kp + k0 + kf * 8;
            uint4 v0 = *(const uint4*)rn;
            uint4 v1 = *(const uint4*)(rn + 4);
            storeB8(SB, nf, kf, n7, v0, v1);
        }
    }
}

__device__ __forceinline__ void mma_tile(const uint32_t* SA, const uint32_t* SB,
                                         float acc[2][8][4], int wm, int wn, int lane) {
#pragma unroll
    for (int ks = 0; ks < 4; ks++) {
        uint32_t a[2][4];
#pragma unroll
        for (int r = 0; r < 2; r++) {
            uint4 t = *(const uint4*)(SA + ((wm * 2 + r) * 4 + ks) * ASTR + lane * 4);
            a[r][0] = t.x; a[r][1] = t.y; a[r][2] = t.z; a[r][3] = t.w;
        }
#pragma unroll
        for (int nf = 0; nf < 8; nf++) {
            uint2 bb = *(const uint2*)(SB + ((wn * 8 + nf) * 4 + ks) * BSTR + lane * 2);
            mma_tf32(acc[0][nf], a[0], bb.x, bb.y);
            mma_tf32(acc[1][nf], a[1], bb.x, bb.y);
        }
    }
}

// ---------------------------------------------------------------------------
// setup kernels
// ---------------------------------------------------------------------------
__device__ __forceinline__ float w_val(int m, int n, int L) {
    float inv4L = 0.25f / (float)L;
    if ((m & 1) == 0) {
        int np = m >> 1;
        float v = (((np + n) & 1) ? -inv4L : inv4L);
        if (n == np) v += 0.25f;
        return v;
    }
    int t = m - 2 * n;
    double th = (double)t * M_PI / (2.0 * (double)L);
    double g = sin((double)(L + 1) * th) / sin(th);
    return (float)(g * 0.25 / (double)L);
}

__global__ void fill_all_kernel(uint32_t* __restrict__ W256,
                                uint32_t* __restrict__ W128,
                                uint32_t* __restrict__ W64) {
    int idx = blockIdx.x * blockDim.x + threadIdx.x;
    if (idx < 131072) {
        int m = idx >> 8, n = idx & 255;
        W256[idx] = f2tf32(w_val(m, n, 256));
    } else if (idx < 163840) {
        int j = idx - 131072;
        int m = j >> 7, n = j & 127;
        W128[j] = f2tf32(w_val(m, n, 128));
    } else if (idx < 172032) {
        int j = idx - 163840;
        int m = j >> 6, n = j & 63;
        W64[j] = f2tf32(w_val(m, n, 64));
    }
}

struct PP { const float* c; uint32_t* Ct; float* bias; int K; };
__global__ void prep_all_kernel(PP p0, PP p1, PP p2, PP p3) {
    int stage = blockIdx.x >> 7;
    int o = blockIdx.x & 127;
    PP p = (stage == 0) ? p0 : (stage == 1) ? p1 : (stage == 2) ? p2 : p3;
    int Kp = p.K * 128;
    for (int cc = threadIdx.x; cc < Kp; cc += blockDim.x) {
        int k = cc >> 7, i = cc & 127;
        p.Ct[(size_t)o * Kp + cc] = f2tf32(p.c[(i * 128 + o) * p.K + k]);
    }
    __shared__ float red[256];
    float s = 0.0f;
    for (int i = threadIdx.x; i < 128; i += blockDim.x) s += p.c[(i * 128 + o) * p.K];
    red[threadIdx.x] = s;
    __syncthreads();
    for (int st = 128; st > 0; st >>= 1) {
        if (threadIdx.x < st) red[threadIdx.x] += red[threadIdx.x + st];
        __syncthreads();
    }
    if (threadIdx.x == 0) p.bias[o] = red[0];
}

__global__ void transpose_all_kernel(const float* __restrict__ x1,
                                     const float* __restrict__ x2,
                                     const float* __restrict__ x3,
                                     uint32_t* __restrict__ xT) {
    __shared__ float t[32][33];
    int bx = blockIdx.x;
    const float* xp;
    uint32_t* xq;
    int L, tidx;
    if (bx < 32)      { L = 256; xp = x1; xq = xT + XT256_OFF; tidx = bx; }
    else if (bx < 48) { L = 128; xp = x2; xq = xT + XT128_OFF; tidx = bx - 32; }
    else              { L = 64;  xp = x3; xq = xT + XT64_OFF;  tidx = bx - 48; }
    int ntiles = L >> 5;
    int n0 = (tidx % ntiles) * 32;
    int o0 = (tidx / ntiles) * 32;
    int b = blockIdx.z;
    int tx = threadIdx.x, ty = threadIdx.y;
    xp += (size_t)b * L * 128;
    xq += (size_t)b * 128 * L;
#pragma unroll
    for (int i = 0; i < 32; i += 8)
        t[ty + i][tx] = xp[(n0 + ty + i) * 128 + o0 + tx];
    __syncthreads();
#pragma unroll
    for (int i = 0; i < 32; i += 8)
        xq[(o0 + ty + i) * L + n0 + tx] = f2tf32(t[tx][ty + i]);
}

// ---------------------------------------------------------------------------
// batched dec interp: d = base - W @ xT, u = tanh(tanh(d)); u0 tail.
// ---------------------------------------------------------------------------
struct IP { const uint32_t* W; const uint32_t* xT; const float* base;
            float* d; float* u; int L; };

__global__ __launch_bounds__(256, 2)
void dec_batched_kernel(IP p3, IP p2, IP p1,
                        const float* __restrict__ x3src, float* __restrict__ u0out) {
    int bx = blockIdx.x;
    int tid = threadIdx.x;
    IP p;
    int mblk, b;
    if (bx < 512)      { p = p3; mblk = bx & 3;          b = bx >> 2; }
    else if (bx < 768) { p = p2; mblk = (bx - 512) & 1;  b = (bx - 512) >> 1; }
    else if (bx < 896) { p = p1; mblk = 0;               b = bx - 768; }
    else {
        int r = bx - 896;
        const float4* s = (const float4*)x3src;
        float4* dst = (float4*)u0out;
#pragma unroll
        for (int j = 0; j < 16; j++) {
            int id = r * 4096 + j * 256 + tid;
            float4 v = s[id];
            v.x = tanhf(tanhf(v.x)); v.y = tanhf(tanhf(v.y));
            v.z = tanhf(tanhf(v.z)); v.w = tanhf(tanhf(v.w));
            dst[id] = v;
        }
        return;
    }

    extern __shared__ uint32_t dynsm[];
    uint32_t* SA0 = dynsm;
    uint32_t* SA1 = SA0 + A_WORDS;
    uint32_t* SB0 = SA1 + A_WORDS;
    uint32_t* SB1 = SB0 + B_WORDS;

    int lane = tid & 31, warp = tid >> 5;
    int wm = warp & 3, wn = warp >> 2;
    int g = lane >> 2, t4 = lane & 3;
    int L = p.L;
    int m0 = mblk * 128;
    const uint32_t* xb = p.xT + (size_t)b * 128 * L;

    float acc[2][8][4];
#pragma unroll
    for (int r = 0; r < 2; r++)
#pragma unroll
        for (int nf = 0; nf < 8; nf++)
#pragma unroll
            for (int s = 0; s < 4; s++) acc[r][nf][s] = 0.0f;

    int nch = L >> 5;
    stage_interp(p.W, xb, m0, L, 0, SA0, SB0, tid);
    __syncthreads();
    for (int ch = 0; ch < nch; ch++) {
        int par = ch & 1;
        uint32_t* SAc = par ? SA1 : SA0;
        uint32_t* SBc = par ? SB1 : SB0;
        if (ch + 1 < nch)
            stage_interp(p.W, xb, m0, L, ch + 1, par ? SA0 : SA1, par ? SB0 : SB1, tid);
        mma_tile(SAc, SBc, acc, wm, wn, lane);
        __syncthreads();
    }

    int TL = 2 * L;
    int cbase = wn * 64 + t4 * 2;
#pragma unroll
    for (int r = 0; r < 2; r++) {
#pragma unroll
        for (int h = 0; h < 2; h++) {
            int ml = m0 + wm * 32 + r * 16 + h * 8 + g;
            int mg = b * TL + ml;
            const float* brow = p.base + (size_t)mg * 128;
            float* drow = p.d + (size_t)mg * 128;
            float* urow = p.u + (size_t)mg * 128;
#pragma unroll
            for (int nf = 0; nf < 8; nf++) {
                int c = cbase + nf * 8;
                float2 bs = *(const float2*)(brow + c);
                float v0 = bs.x - acc[r][nf][h * 2 + 0];
                float v1 = bs.y - acc[r][nf][h * 2 + 1];
                *(float2*)(drow + c) = make_float2(v0, v1);
                urow[c]     = tanhf(tanhf(v0));
                urow[c + 1] = tanhf(tanhf(v1));
            }
        }
    }
}

// ---------------------------------------------------------------------------
// batched mkan
// ---------------------------------------------------------------------------
struct MP { const float* u; const uint32_t* Bm; const float* bias;
            const float* x; const float* w; float* out;
            uint32_t* xTout; int Kp; int Ntime; };

__global__ __launch_bounds__(256, 2)
void mkan_batched_kernel(MP s3, MP s2, MP s1, MP s0) {
    int bx = blockIdx.x;
    MP p;
    int m0;
    if (bx < 512)      { p = s3; m0 = bx * 128; }
    else if (bx < 768) { p = s2; m0 = (bx - 512) * 128; }
    else if (bx < 896) { p = s1; m0 = (bx - 768) * 128; }
    else               { p = s0; m0 = (bx - 896) * 128; }

    extern __shared__ uint32_t dynsm[];
    uint32_t* SA0 = dynsm;
    uint32_t* SA1 = SA0 + A_WORDS;
    uint32_t* SB0 = SA1 + A_WORDS;
    uint32_t* SB1 = SB0 + B_WORDS;
    float* Ws  = (float*)(SB1 + B_WORDS);
    float* Bsh = Ws + 384;

    int tid = threadIdx.x, lane = tid & 31, warp = tid >> 5;
    int wm = warp & 3, wn = warp >> 2;
    int g = lane >> 2, t4 = lane & 3;

    for (int j = tid; j < 384; j += 256) Ws[j] = p.w[j];
    if (tid < 128) Bsh[tid] = p.bias[tid];

    float acc[2][8][4];
#pragma unroll
    for (int r = 0; r < 2; r++)
#pragma unroll
        for (int nf = 0; nf < 8; nf++)
#pragma unroll
            for (int s = 0; s < 4; s++) acc[r][nf][s] = 0.0f;

    int nch = p.Kp >> 5;
    const int first = 4;               // kk = 0 folded into bias
    stage_mkan(p.u, p.Bm, m0, p.Kp, first, SA0, SB0, tid);
    __syncthreads();
    for (int ch = first; ch < nch; ch++) {
        int par = (ch - first) & 1;
        uint32_t* SAc = par ? SA1 : SA0;
        uint32_t* SBc = par ? SB1 : SB0;
        if (ch + 1 < nch)
            stage_mkan(p.u, p.Bm, m0, p.Kp, ch + 1, par ? SA0 : SA1, par ? SB0 : SB1, tid);
        mma_tile(SAc, SBc, acc, wm, wn, lane);
        __syncthreads();
    }

    int Ntime = p.Ntime;
    int cbase = wn * 64 + t4 * 2;
#pragma unroll
    for (int r = 0; r < 2; r++) {
#pragma unroll
        for (int h = 0; h < 2; h++) {
            int m = m0 + wm * 32 + r * 16 + h * 8 + g;
            int n = m & (Ntime - 1);
            int bb = m / Ntime;
            const float* xr = p.x + (size_t)m * 128;
            float* orow = p.out + (size_t)m * 128;
            bool hasp = n > 0, hasn = n < (Ntime - 1);
#pragma unroll
            for (int nf = 0; nf < 8; nf++) {
                int c = cbase + nf * 8;
                float v0 = acc[r][nf][h * 2 + 0] + Bsh[c];
                float v1 = acc[r][nf][h * 2 + 1] + Bsh[c + 1];
                float2 cur = *(const float2*)(xr + c);
                float2 prv = hasp ? *(const float2*)(xr + c - 128) : make_float2(0.f, 0.f);
                float2 nxt = hasn ? *(const float2*)(xr + c + 128) : make_float2(0.f, 0.f);
                v0 += cur.x * Ws[c * 3 + 1] + prv.x * Ws[c * 3] + nxt.x * Ws[c * 3 + 2];
                v1 += cur.y * Ws[c * 3 + 4] + prv.y * Ws[c * 3 + 3] + nxt.y * Ws[c * 3 + 5];
                *(float2*)(orow + c) = make_float2(v0, v1);
                if (p.xTout) {
                    p.xTout[((size_t)bb * 128 + c) * Ntime + n]     = f2tf32(v0);
                    p.xTout[((size_t)bb * 128 + c + 1) * Ntime + n] = f2tf32(v1);
                }
            }
        }
    }
}

// ---------------------------------------------------------------------------
// mix interp
// ---------------------------------------------------------------------------
__global__ __launch_bounds__(256, 2)
void interp_mma_kernel(const uint32_t* __restrict__ W, const uint32_t* __restrict__ xT,
                       const float* __restrict__ base, float* __restrict__ out,
                       int L, uint32_t* __restrict__ xTout) {
    extern __shared__ uint32_t dynsm[];
    uint32_t* SA0 = dynsm;
    uint32_t* SA1 = SA0 + A_WORDS;
    uint32_t* SB0 = SA1 + A_WORDS;
    uint32_t* SB1 = SB0 + B_WORDS;

    int tid = threadIdx.x, lane = tid & 31, warp = tid >> 5;
    int wm = warp & 3, wn = warp >> 2;
    int g = lane >> 2, t4 = lane & 3;
    int b = blockIdx.y;
    int m0 = blockIdx.x * 128;
    const uint32_t* xb = xT + (size_t)b * 128 * L;

    float acc[2][8][4];
#pragma unroll
    for (int r = 0; r < 2; r++)
#pragma unroll
        for (int nf = 0; nf < 8; nf++)
#pragma unroll
            for (int s = 0; s < 4; s++) acc[r][nf][s] = 0.0f;

    int nch = L >> 5;
    stage_interp(W, xb, m0, L, 0, SA0, SB0, tid);
    __syncthreads();
    for (int ch = 0; ch < nch; ch++) {
        int par = ch & 1;
        uint32_t* SAc = par ? SA1 : SA0;
        uint32_t* SBc = par ? SB1 : SB0;
        if (ch + 1 < nch)
            stage_interp(W, xb, m0, L, ch + 1, par ? SA0 : SA1, par ? SB0 : SB1, tid);
        mma_tile(SAc, SBc, acc, wm, wn, lane);
        __syncthreads();
    }

    int TL = 2 * L;
    int cbase = wn * 64 + t4 * 2;
#pragma unroll
    for (int r = 0; r < 2; r++) {
#pragma unroll
        for (int h = 0; h < 2; h++) {
            int ml = m0 + wm * 32 + r * 16 + h * 8 + g;
            int mg = b * TL + ml;
            const float* brow = base + (size_t)mg * 128;
            float* orow = out + (size_t)mg * 128;
#pragma unroll
            for (int nf = 0; nf < 8; nf++) {
                int c = cbase + nf * 8;
                float2 bs = *(const float2*)(brow + c);
                float v0 = acc[r][nf][h * 2 + 0] + bs.x;
                float v1 = acc[r][nf][h * 2 + 1] + bs.y;
                *(float2*)(orow + c) = make_float2(v0, v1);
                if (xTout) {
                    xTout[((size_t)b * 128 + c) * TL + ml]     = f2tf32(v0);
                    xTout[((size_t)b * 128 + c + 1) * TL + ml] = f2tf32(v1);
                }
            }
        }
    }
}

// ---------------------------------------------------------------------------
extern "C" void kernel_launch(void* const* d_in, const int* in_sizes, int n_in,
                              void* d_out, int out_size) {
    const float* x0 = (const float*)d_in[0];
    const float* x1 = (const float*)d_in[1];
    const float* x2 = (const float*)d_in[2];
    const float* x3 = (const float*)d_in[3];
    const float* c0 = (const float*)d_in[4];
    const float* w0 = (const float*)d_in[5];
    const float* c1 = (const float*)d_in[6];
    const float* w1 = (const float*)d_in[7];
    const float* c2 = (const float*)d_in[8];
    const float* w2 = (const float*)d_in[9];
    const float* c3 = (const float*)d_in[10];
    const float* w3 = (const float*)d_in[11];
    float* out = (float*)d_out;

    uint32_t *pW64, *pW128, *pW256, *pCt0, *pCt1, *pCt2, *pCt3, *pxT, *pxT2;
    float *pbias, *pd3, *pd2, *pd1, *pu3, *pu2, *pu1, *pu0, *poh1, *poh2, *poh3;
    cudaGetSymbolAddress((void**)&pW64,  g_W64);
    cudaGetSymbolAddress((void**)&pW128, g_W128);
    cudaGetSymbolAddress((void**)&pW256, g_W256);
    cudaGetSymbolAddress((void**)&pCt0,  g_Ct0);
    cudaGetSymbolAddress((void**)&pCt1,  g_Ct1);
    cudaGetSymbolAddress((void**)&pCt2,  g_Ct2);
    cudaGetSymbolAddress((void**)&pCt3,  g_Ct3);
    cudaGetSymbolAddress((void**)&pbias, g_bias);
    cudaGetSymbolAddress((void**)&pd3,   g_d3);
    cudaGetSymbolAddress((void**)&pd2,   g_d2);
    cudaGetSymbolAddress((void**)&pd1,   g_d1);
    cudaGetSymbolAddress((void**)&pu3,   g_u3);
    cudaGetSymbolAddress((void**)&pu2,   g_u2);
    cudaGetSymbolAddress((void**)&pu1,   g_u1);
    cudaGetSymbolAddress((void**)&pu0,   g_u0);
    cudaGetSymbolAddress((void**)&poh1,  g_oh1);
    cudaGetSymbolAddress((void**)&poh2,  g_oh2);
    cudaGetSymbolAddress((void**)&poh3,  g_oh3);
    cudaGetSymbolAddress((void**)&pxT,   g_xT);
    cudaGetSymbolAddress((void**)&pxT2,  g_xT2);

    cudaFuncSetAttribute(dec_batched_kernel,
                         cudaFuncAttributeMaxDynamicSharedMemorySize, SMEM_BYTES_INTERP);
    cudaFuncSetAttribute(mkan_batched_kernel,
                         cudaFuncAttributeMaxDynamicSharedMemorySize, SMEM_BYTES_MKAN);
    cudaFuncSetAttribute(interp_mma_kernel,
                         cudaFuncAttributeMaxDynamicSharedMemorySize, SMEM_BYTES_INTERP);

    /*0*/ fill_all_kernel<<<(172032 + 255) / 256, 256>>>(pW256, pW128, pW64);
    /*1*/ {
        PP p0 = {c0, pCt0, pbias + 0 * 128, 2};
        PP p1 = {c1, pCt1, pbias + 1 * 128, 3};
        PP p2 = {c2, pCt2, pbias + 2 * 128, 4};
        PP p3 = {c3, pCt3, pbias + 3 * 128, 5};
        prep_all_kernel<<<512, 256>>>(p0, p1, p2, p3);
    }
    /*2*/ transpose_all_kernel<<<dim3(56, 1, 128), dim3(32, 8)>>>(x1, x2, x3, pxT);
    /*3*/ {
        IP p3s = {pW256, pxT + XT256_OFF, x0, pd3, pu3, 256};
        IP p2s = {pW128, pxT + XT128_OFF, x1, pd2, pu2, 128};
        IP p1s = {pW64,  pxT + XT64_OFF,  x2, pd1, pu1, 64};
        dec_batched_kernel<<<960, 256, SMEM_BYTES_INTERP>>>(p3s, p2s, p1s, x3, pu0);
    }
    /*4*/ {
        MP s3 = {pu3, pCt3, pbias + 3 * 128, pd3, w3, poh3, nullptr, 640, 512};
        MP s2 = {pu2, pCt2, pbias + 2 * 128, pd2, w2, poh2, nullptr, 512, 256};
        MP s1 = {pu1, pCt1, pbias + 1 * 128, pd1, w1, poh1, nullptr, 384, 128};
        MP s0 = {pu0, pCt0, pbias + 0 * 128, x3, w0, out + OFF64, pxT2, 256, 64};
        mkan_batched_kernel<<<960, 256, SMEM_BYTES_MKAN>>>(s3, s2, s1, s0);
    }
    /*5*/ { dim3 g(1, 128);
            interp_mma_kernel<<<g, 256, SMEM_BYTES_INTERP>>>(pW64,  pxT2, poh1, out + OFF128,  64, pxT); }
    /*6*/ { dim3 g(2, 128);
            interp_mma_kernel<<<g, 256, SMEM_BYTES_INTERP>>>(pW128, pxT,  poh2, out + OFF256, 128, pxT2); }
    /*7*/ { dim3 g(4, 128);
            interp_mma_kernel<<<g, 256, SMEM_BYTES_INTERP>>>(pW256, pxT2, poh3, out + OFF512, 256, nullptr); }

    (void)in_sizes; (void)n_in; (void)out_size;
}

// round 7
// speedup vs baseline: 4.9364x; 1.1242x over previous
#include <cuda_runtime.h>
#include <math.h>
#include <cstdint>

// ---------------------------------------------------------------------------
// TimeKAN forward, mma.sync tf32.
// Interp GEMMs use only the ODD rows of the Dirichlet matrix (L x L);
// even rows are closed-form: 0.25*x_low[t] + (-1)^t * S/(4L), S = sum (-1)^n x[n],
// with S computed during B staging (free) + shuffle reduction.
// cheby_kan GEMM: T_0 folded into bias; chunk order (i-block outer, order inner)
// for L1 reuse of u. dw_conv fused into mkan epilogue.
// ---------------------------------------------------------------------------

#define OFF512 0
#define OFF256 8388608
#define OFF128 12582912
#define OFF64  14680064

// ODD-row interp matrices (L x L), tf32 patterns
__device__ uint32_t g_W64 [64 * 64];
__device__ uint32_t g_W128[128 * 128];
__device__ uint32_t g_W256[256 * 256];

__device__ uint32_t g_Ct0[128 * 256];
__device__ uint32_t g_Ct1[128 * 384];
__device__ uint32_t g_Ct2[128 * 512];
__device__ uint32_t g_Ct3[128 * 640];
__device__ float    g_bias[4 * 128];

__device__ float g_d3[128 * 512 * 128];
__device__ float g_d2[128 * 256 * 128];
__device__ float g_d1[128 * 128 * 128];
__device__ float g_u3[128 * 512 * 128];
__device__ float g_u2[128 * 256 * 128];
__device__ float g_u1[128 * 128 * 128];
__device__ float g_u0[128 *  64 * 128];

__device__ float g_oh1[128 * 128 * 128];
__device__ float g_oh2[128 * 256 * 128];
__device__ float g_oh3[128 * 512 * 128];

__device__ uint32_t g_xT [128 * 128 * 512];
__device__ uint32_t g_xT2[128 * 128 * 256];

#define XT256_OFF 0
#define XT128_OFF 4194304
#define XT64_OFF  6291456

#define ASTR 132
#define BSTR 68
#define A_WORDS (32 * ASTR)
#define B_WORDS (64 * BSTR)
#define SMEM_BYTES_INTERP ((2 * A_WORDS + 2 * B_WORDS + 128) * 4)
#define SMEM_BYTES_MKAN   ((2 * A_WORDS + 2 * B_WORDS + 512) * 4)

// ---------------------------------------------------------------------------
__device__ __forceinline__ uint32_t f2tf32(float f) {
    uint32_t r;
    asm("cvt.rna.tf32.f32 %0, %1;" : "=r"(r) : "f"(f));
    return r;
}
__device__ __forceinline__ float u2f(uint32_t u) { return __uint_as_float(u); }

__device__ __forceinline__ void mma_tf32(float c[4], const uint32_t a[4],
                                         uint32_t b0, uint32_t b1) {
    asm volatile(
        "mma.sync.aligned.m16n8k8.row.col.f32.tf32.tf32.f32 "
        "{%0,%1,%2,%3}, {%4,%5,%6,%7}, {%8,%9}, {%0,%1,%2,%3};"
        : "+f"(c[0]), "+f"(c[1]), "+f"(c[2]), "+f"(c[3])
        : "r"(a[0]), "r"(a[1]), "r"(a[2]), "r"(a[3]), "r"(b0), "r"(b1));
}
__device__ __forceinline__ float chebT(int k, float uu) {
    if (k == 1) return uu;
    if (k == 2) return fmaf(2.0f * uu, uu, -1.0f);
    if (k == 3) return uu * fmaf(4.0f * uu, uu, -3.0f);
    float s = uu * uu;
    return fmaf(8.0f * s, s - 1.0f, 1.0f);   // k == 4
}

__device__ __forceinline__ void storeA16(uint32_t* SA, int mf, int kf, int m7,
                                         uint4 v0, uint4 v1, uint4 v2, uint4 v3) {
    uint4* p = (uint4*)(SA + (mf * 4 + kf) * ASTR + m7 * 16);
    p[0] = make_uint4(v0.x, v2.x, v1.x, v3.x);
    p[1] = make_uint4(v0.y, v2.y, v1.y, v3.y);
    p[2] = make_uint4(v0.z, v2.z, v1.z, v3.z);
    p[3] = make_uint4(v0.w, v2.w, v1.w, v3.w);
}
__device__ __forceinline__ void storeB8(uint32_t* SB, int nf, int kf, int n7,
                                        uint4 v0, uint4 v1) {
    uint4* p = (uint4*)(SB + (nf * 4 + kf) * BSTR + n7 * 8);
    p[0] = make_uint4(v0.x, v1.x, v0.y, v1.y);
    p[1] = make_uint4(v0.z, v1.z, v0.w, v1.w);
}

__device__ __forceinline__ void mma_tile(const uint32_t* SA, const uint32_t* SB,
                                         float acc[2][8][4], int wm, int wn, int lane) {
#pragma unroll
    for (int ks = 0; ks < 4; ks++) {
        uint32_t a[2][4];
#pragma unroll
        for (int r = 0; r < 2; r++) {
            uint4 t = *(const uint4*)(SA + ((wm * 2 + r) * 4 + ks) * ASTR + lane * 4);
            a[r][0] = t.x; a[r][1] = t.y; a[r][2] = t.z; a[r][3] = t.w;
        }
#pragma unroll
        for (int nf = 0; nf < 8; nf++) {
            uint2 bb = *(const uint2*)(SB + ((wn * 8 + nf) * 4 + ks) * BSTR + lane * 2);
            mma_tf32(acc[0][nf], a[0], bb.x, bb.y);
            mma_tf32(acc[1][nf], a[1], bb.x, bb.y);
        }
    }
}

// interp staging: A = odd-row W (masked rows for L<tile), B = xT; signed sum acc
__device__ __forceinline__ void stage_iodd(const uint32_t* __restrict__ W,
                                           const uint32_t* __restrict__ xb,
                                           int m0, int L, int amask, int ch,
                                           uint32_t* SA, uint32_t* SB, int tid,
                                           float& s0, float& s1) {
    int k0 = ch << 5;
    {
        int kf = tid & 3, m7 = (tid >> 2) & 7, mf = tid >> 5;
        int row = (m0 + mf * 16 + m7) & amask;
        const uint32_t* r0 = W + (size_t)row * L + k0 + kf * 8;
        const uint32_t* r1 = r0 + (size_t)8 * L;
        uint4 v0 = *(const uint4*)r0;
        uint4 v1 = *(const uint4*)(r0 + 4);
        uint4 v2 = *(const uint4*)r1;
        uint4 v3 = *(const uint4*)(r1 + 4);
        storeA16(SA, mf, kf, m7, v0, v1, v2, v3);
    }
    {
        int kf = tid & 3, nfl = (tid >> 2) & 1, n7 = (tid >> 3) & 7, nfh = tid >> 6;
#pragma unroll
        for (int uu = 0; uu < 2; uu++) {
            int nf = nfh * 2 + nfl + uu * 8;
            const uint32_t* rn = xb + (size_t)(nf * 8 + n7) * L + k0 + kf * 8;
            uint4 v0 = *(const uint4*)rn;
            uint4 v1 = *(const uint4*)(rn + 4);
            storeB8(SB, nf, kf, n7, v0, v1);
            float sv = u2f(v0.x) - u2f(v0.y) + u2f(v0.z) - u2f(v0.w)
                     + u2f(v1.x) - u2f(v1.y) + u2f(v1.z) - u2f(v1.w);
            if (uu) s1 += sv; else s0 += sv;
        }
    }
}

// mkan staging: A = chebT(kk, u[:, i0..]) on the fly, B = Ct row slice at k0
__device__ __forceinline__ void stage_mkan(const float* __restrict__ u,
                                           const uint32_t* __restrict__ Bm,
                                           int m0, int Kp, int i0, int k0, int kk,
                                           uint32_t* SA, uint32_t* SB, int tid) {
    {
        int kf = tid & 3, m7 = (tid >> 2) & 7, mf = tid >> 5;
        const float* r0 = u + (size_t)(m0 + mf * 16 + m7) * 128 + i0 + kf * 8;
        const float* r1 = r0 + 8 * 128;
        float4 f0 = *(const float4*)r0;
        float4 f1 = *(const float4*)(r0 + 4);
        float4 f2 = *(const float4*)r1;
        float4 f3 = *(const float4*)(r1 + 4);
        uint4 v0, v1, v2, v3;
        v0.x = f2tf32(chebT(kk, f0.x)); v0.y = f2tf32(chebT(kk, f0.y));
        v0.z = f2tf32(chebT(kk, f0.z)); v0.w = f2tf32(chebT(kk, f0.w));
        v1.x = f2tf32(chebT(kk, f1.x)); v1.y = f2tf32(chebT(kk, f1.y));
        v1.z = f2tf32(chebT(kk, f1.z)); v1.w = f2tf32(chebT(kk, f1.w));
        v2.x = f2tf32(chebT(kk, f2.x)); v2.y = f2tf32(chebT(kk, f2.y));
        v2.z = f2tf32(chebT(kk, f2.z)); v2.w = f2tf32(chebT(kk, f2.w));
        v3.x = f2tf32(chebT(kk, f3.x)); v3.y = f2tf32(chebT(kk, f3.y));
        v3.z = f2tf32(chebT(kk, f3.z)); v3.w = f2tf32(chebT(kk, f3.w));
        storeA16(SA, mf, kf, m7, v0, v1, v2, v3);
    }
    {
        int kf = tid & 3, nfl = (tid >> 2) & 1, n7 = (tid >> 3) & 7, nfh = tid >> 6;
#pragma unroll
        for (int uu = 0; uu < 2; uu++) {
            int nf = nfh * 2 + nfl + uu * 8;
            const uint32_t* rn = Bm + (size_t)(nf * 8 + n7) * Kp + k0 + kf * 8;
            uint4 v0 = *(const uint4*)rn;
            uint4 v1 = *(const uint4*)(rn + 4);
            storeB8(SB, nf, kf, n7, v0, v1);
        }
    }
}

// ---------------------------------------------------------------------------
// odd-interp core: out[b,2t+1,:] = hi[2t+1] + alpha*GEMM; out[b,2t,:] =
// hi[2t] + alpha*(0.25*lo[t] + (-1)^t*inv4L*S). Optional u/xTout epilogues.
// ---------------------------------------------------------------------------
__device__ __forceinline__ void interp_odd_core(
    const uint32_t* __restrict__ W, const uint32_t* __restrict__ xT,
    const float* __restrict__ hi, const float* __restrict__ lo,
    float* __restrict__ out, float* __restrict__ uout, uint32_t* __restrict__ xTout,
    int L, float alpha, int m0, int b, uint32_t* dynsm)
{
    uint32_t* SA0 = dynsm;
    uint32_t* SA1 = SA0 + A_WORDS;
    uint32_t* SB0 = SA1 + A_WORDS;
    uint32_t* SB1 = SB0 + B_WORDS;
    float* Ssh = (float*)(SB1 + B_WORDS);

    int tid = threadIdx.x, lane = tid & 31, warp = tid >> 5;
    int wm = warp & 3, wn = warp >> 2;
    int g = lane >> 2, t4 = lane & 3;
    const uint32_t* xb = xT + (size_t)b * 128 * L;
    int amask = L - 1;

    float acc[2][8][4];
#pragma unroll
    for (int r = 0; r < 2; r++)
#pragma unroll
        for (int nf = 0; nf < 8; nf++)
#pragma unroll
            for (int s = 0; s < 4; s++) acc[r][nf][s] = 0.0f;
    float s0 = 0.0f, s1 = 0.0f;

    int nch = L >> 5;
    stage_iodd(W, xb, m0, L, amask, 0, SA0, SB0, tid, s0, s1);
    __syncthreads();
    for (int ch = 0; ch < nch; ch++) {
        int par = ch & 1;
        uint32_t* SAc = par ? SA1 : SA0;
        uint32_t* SBc = par ? SB1 : SB0;
        if (ch + 1 < nch)
            stage_iodd(W, xb, m0, L, amask, ch + 1,
                       par ? SA0 : SA1, par ? SB0 : SB1, tid, s0, s1);
        mma_tile(SAc, SBc, acc, wm, wn, lane);
        __syncthreads();
    }

    // reduce signed sums over kf (lane bits 0..1) and publish S per channel
    s0 += __shfl_xor_sync(0xFFFFFFFFu, s0, 1);
    s0 += __shfl_xor_sync(0xFFFFFFFFu, s0, 2);
    s1 += __shfl_xor_sync(0xFFFFFFFFu, s1, 1);
    s1 += __shfl_xor_sync(0xFFFFFFFFu, s1, 2);
    if ((tid & 3) == 0) {
        int nfl = (tid >> 2) & 1, n7 = (tid >> 3) & 7, nfh = tid >> 6;
        Ssh[(nfh * 2 + nfl) * 8 + n7]       = s0;
        Ssh[(nfh * 2 + nfl + 8) * 8 + n7]   = s1;
    }
    __syncthreads();

    int TL = 2 * L;
    float inv4L = 0.25f / (float)L;
    int cbase = wn * 64 + t4 * 2;
#pragma unroll
    for (int r = 0; r < 2; r++) {
#pragma unroll
        for (int h = 0; h < 2; h++) {
            int tl = m0 + wm * 32 + r * 16 + h * 8 + g;
            if (tl >= L) continue;
            float sgn = (tl & 1) ? -inv4L : inv4L;
            size_t rowe = ((size_t)b * TL + 2 * tl) * 128;
            const float* hie = hi + rowe;
            const float* hio = hi + rowe + 128;
            const float* lor = lo + ((size_t)b * L + tl) * 128;
            float* oute = out + rowe;
            float* outo = out + rowe + 128;
#pragma unroll
            for (int nf = 0; nf < 8; nf++) {
                int c = cbase + nf * 8;
                float a0 = acc[r][nf][h * 2 + 0];
                float a1 = acc[r][nf][h * 2 + 1];
                float2 ho = *(const float2*)(hio + c);
                float vo0 = fmaf(alpha, a0, ho.x);
                float vo1 = fmaf(alpha, a1, ho.y);
                float2 he = *(const float2*)(hie + c);
                float2 xl = *(const float2*)(lor + c);
                float ie0 = fmaf(0.25f, xl.x, sgn * Ssh[c]);
                float ie1 = fmaf(0.25f, xl.y, sgn * Ssh[c + 1]);
                float ve0 = fmaf(alpha, ie0, he.x);
                float ve1 = fmaf(alpha, ie1, he.y);
                *(float2*)(oute + c) = make_float2(ve0, ve1);
                *(float2*)(outo + c) = make_float2(vo0, vo1);
                if (uout) {
                    *(float2*)(uout + rowe + c) =
                        make_float2(tanhf(tanhf(ve0)), tanhf(tanhf(ve1)));
                    *(float2*)(uout + rowe + 128 + c) =
                        make_float2(tanhf(tanhf(vo0)), tanhf(tanhf(vo1)));
                }
                if (xTout) {
                    *(uint2*)(xTout + ((size_t)b * 128 + c) * TL + 2 * tl) =
                        make_uint2(f2tf32(ve0), f2tf32(vo0));
                    *(uint2*)(xTout + ((size_t)b * 128 + c + 1) * TL + 2 * tl) =
                        make_uint2(f2tf32(ve1), f2tf32(vo1));
                }
            }
        }
    }
}

// ---------------------------------------------------------------------------
// setup kernels
// ---------------------------------------------------------------------------
__device__ __forceinline__ float w_odd(int t, int n, int L) {
    int tt = 2 * t + 1 - 2 * n;
    double th = (double)tt * M_PI / (2.0 * (double)L);
    double gg = sin((double)(L + 1) * th) / sin(th);
    return (float)(gg * 0.25 / (double)L);
}

__global__ void fill_all_kernel(uint32_t* __restrict__ W256,
                                uint32_t* __restrict__ W128,
                                uint32_t* __restrict__ W64) {
    int idx = blockIdx.x * blockDim.x + threadIdx.x;
    if (idx < 65536) {
        int t = idx >> 8, n = idx & 255;
        W256[idx] = f2tf32(w_odd(t, n, 256));
    } else if (idx < 81920) {
        int j = idx - 65536;
        int t = j >> 7, n = j & 127;
        W128[j] = f2tf32(w_odd(t, n, 128));
    } else if (idx < 86016) {
        int j = idx - 81920;
        int t = j >> 6, n = j & 63;
        W64[j] = f2tf32(w_odd(t, n, 64));
    }
}

struct PP { const float* c; uint32_t* Ct; float* bias; int K; };
__global__ void prep_all_kernel(PP p0, PP p1, PP p2, PP p3) {
    int stage = blockIdx.x >> 7;
    int o = blockIdx.x & 127;
    PP p = (stage == 0) ? p0 : (stage == 1) ? p1 : (stage == 2) ? p2 : p3;
    int Kp = p.K * 128;
    for (int cc = threadIdx.x; cc < Kp; cc += blockDim.x) {
        int k = cc >> 7, i = cc & 127;
        p.Ct[(size_t)o * Kp + cc] = f2tf32(p.c[(i * 128 + o) * p.K + k]);
    }
    __shared__ float red[256];
    float s = 0.0f;
    for (int i = threadIdx.x; i < 128; i += blockDim.x) s += p.c[(i * 128 + o) * p.K];
    red[threadIdx.x] = s;
    __syncthreads();
    for (int st = 128; st > 0; st >>= 1) {
        if (threadIdx.x < st) red[threadIdx.x] += red[threadIdx.x + st];
        __syncthreads();
    }
    if (threadIdx.x == 0) p.bias[o] = red[0];
}

__global__ void transpose_all_kernel(const float* __restrict__ x1,
                                     const float* __restrict__ x2,
                                     const float* __restrict__ x3,
                                     uint32_t* __restrict__ xT) {
    __shared__ float t[32][33];
    int bx = blockIdx.x;
    const float* xp;
    uint32_t* xq;
    int L, tidx;
    if (bx < 32)      { L = 256; xp = x1; xq = xT + XT256_OFF; tidx = bx; }
    else if (bx < 48) { L = 128; xp = x2; xq = xT + XT128_OFF; tidx = bx - 32; }
    else              { L = 64;  xp = x3; xq = xT + XT64_OFF;  tidx = bx - 48; }
    int ntiles = L >> 5;
    int n0 = (tidx % ntiles) * 32;
    int o0 = (tidx / ntiles) * 32;
    int b = blockIdx.z;
    int tx = threadIdx.x, ty = threadIdx.y;
    xp += (size_t)b * L * 128;
    xq += (size_t)b * 128 * L;
#pragma unroll
    for (int i = 0; i < 32; i += 8)
        t[ty + i][tx] = xp[(n0 + ty + i) * 128 + o0 + tx];
    __syncthreads();
#pragma unroll
    for (int i = 0; i < 32; i += 8)
        xq[(o0 + ty + i) * L + n0 + tx] = f2tf32(t[tx][ty + i]);
}

// ---------------------------------------------------------------------------
// batched dec: d = hi - interp(lo), u = tanh(tanh(d)); plus u0 tail
// ---------------------------------------------------------------------------
struct DP { const uint32_t* W; const uint32_t* xT; const float* hi;
            const float* lo; float* d; float* u; int L; };

__global__ __launch_bounds__(256, 2)
void dec_batched_kernel(DP s3, DP s2, DP s1,
                        const float* __restrict__ x3src, float* __restrict__ u0out) {
    extern __shared__ uint32_t dynsm[];
    int bx = blockIdx.x;
    int tid = threadIdx.x;
    DP p;
    int m0, b;
    if (bx < 256)      { p = s3; m0 = (bx >> 7) * 128; b = bx & 127; }
    else if (bx < 384) { p = s2; m0 = 0; b = bx - 256; }
    else if (bx < 512) { p = s1; m0 = 0; b = bx - 384; }
    else {
        int r = bx - 512;
        const float4* s = (const float4*)x3src;
        float4* dst = (float4*)u0out;
#pragma unroll
        for (int j = 0; j < 16; j++) {
            int id = r * 4096 + j * 256 + tid;
            float4 v = s[id];
            v.x = tanhf(tanhf(v.x)); v.y = tanhf(tanhf(v.y));
            v.z = tanhf(tanhf(v.z)); v.w = tanhf(tanhf(v.w));
            dst[id] = v;
        }
        return;
    }
    interp_odd_core(p.W, p.xT, p.hi, p.lo, p.d, p.u, nullptr,
                    p.L, -1.0f, m0, b, dynsm);
}

// ---------------------------------------------------------------------------
// mix: out = oh + interp(lo)
// ---------------------------------------------------------------------------
__global__ __launch_bounds__(256, 2)
void mix_odd_kernel(const uint32_t* __restrict__ W, const uint32_t* __restrict__ xT,
                    const float* __restrict__ oh, const float* __restrict__ lo,
                    float* __restrict__ out, uint32_t* __restrict__ xTout, int L) {
    extern __shared__ uint32_t dynsm[];
    interp_odd_core(W, xT, oh, lo, out, nullptr, xTout,
                    L, 1.0f, blockIdx.x * 128, blockIdx.y, dynsm);
}

// ---------------------------------------------------------------------------
// batched mkan (i-block outer, cheb order inner for u L1 reuse)
// ---------------------------------------------------------------------------
struct MP { const float* u; const uint32_t* Bm; const float* bias;
            const float* x; const float* w; float* out;
            uint32_t* xTout; int Kp; int Ntime; };

__global__ __launch_bounds__(256, 2)
void mkan_batched_kernel(MP s3, MP s2, MP s1, MP s0) {
    int bx = blockIdx.x;
    MP p;
    int m0;
    if (bx < 512)      { p = s3; m0 = bx * 128; }
    else if (bx < 768) { p = s2; m0 = (bx - 512) * 128; }
    else if (bx < 896) { p = s1; m0 = (bx - 768) * 128; }
    else               { p = s0; m0 = (bx - 896) * 128; }

    extern __shared__ uint32_t dynsm[];
    uint32_t* SA0 = dynsm;
    uint32_t* SA1 = SA0 + A_WORDS;
    uint32_t* SB0 = SA1 + A_WORDS;
    uint32_t* SB1 = SB0 + B_WORDS;
    float* Ws  = (float*)(SB1 + B_WORDS);
    float* Bsh = Ws + 384;

    int tid = threadIdx.x, lane = tid & 31, warp = tid >> 5;
    int wm = warp & 3, wn = warp >> 2;
    int g = lane >> 2, t4 = lane & 3;

    for (int j = tid; j < 384; j += 256) Ws[j] = p.w[j];
    if (tid < 128) Bsh[tid] = p.bias[tid];

    float acc[2][8][4];
#pragma unroll
    for (int r = 0; r < 2; r++)
#pragma unroll
        for (int nf = 0; nf < 8; nf++)
#pragma unroll
            for (int s = 0; s < 4; s++) acc[r][nf][s] = 0.0f;

    int km1 = (p.Kp >> 7) - 1;        // orders 1..km1 (T_0 in bias)
    int Q = km1 * 4;
    // chunk (ib, kk): i0 = ib*32, k0 = kk*128 + ib*32
    stage_mkan(p.u, p.Bm, m0, p.Kp, 0, 128, 1, SA0, SB0, tid);
    __syncthreads();
    int cib = 0, ckk = 1;
    for (int q = 0; q < Q; q++) {
        int par = q & 1;
        uint32_t* SAc = par ? SA1 : SA0;
        uint32_t* SBc = par ? SB1 : SB0;
        int nkk = ckk + 1, nib = cib;
        if (nkk > km1) { nkk = 1; nib++; }
        if (q + 1 < Q)
            stage_mkan(p.u, p.Bm, m0, p.Kp, nib << 5, (nkk << 7) + (nib << 5), nkk,
                       par ? SA0 : SA1, par ? SB0 : SB1, tid);
        mma_tile(SAc, SBc, acc, wm, wn, lane);
        __syncthreads();
        ckk = nkk; cib = nib;
    }

    int Ntime = p.Ntime;
    int cbase = wn * 64 + t4 * 2;
#pragma unroll
    for (int r = 0; r < 2; r++) {
#pragma unroll
        for (int h = 0; h < 2; h++) {
            int m = m0 + wm * 32 + r * 16 + h * 8 + g;
            int n = m & (Ntime - 1);
            int bb = m / Ntime;
            const float* xr = p.x + (size_t)m * 128;
            float* orow = p.out + (size_t)m * 128;
            bool hasp = n > 0, hasn = n < (Ntime - 1);
#pragma unroll
            for (int nf = 0; nf < 8; nf++) {
                int c = cbase + nf * 8;
                float v0 = acc[r][nf][h * 2 + 0] + Bsh[c];
                float v1 = acc[r][nf][h * 2 + 1] + Bsh[c + 1];
                float2 cur = *(const float2*)(xr + c);
                float2 prv = hasp ? *(const float2*)(xr + c - 128) : make_float2(0.f, 0.f);
                float2 nxt = hasn ? *(const float2*)(xr + c + 128) : make_float2(0.f, 0.f);
                v0 += cur.x * Ws[c * 3 + 1] + prv.x * Ws[c * 3] + nxt.x * Ws[c * 3 + 2];
                v1 += cur.y * Ws[c * 3 + 4] + prv.y * Ws[c * 3 + 3] + nxt.y * Ws[c * 3 + 5];
                *(float2*)(orow + c) = make_float2(v0, v1);
                if (p.xTout) {
                    p.xTout[((size_t)bb * 128 + c) * Ntime + n]     = f2tf32(v0);
                    p.xTout[((size_t)bb * 128 + c + 1) * Ntime + n] = f2tf32(v1);
                }
            }
        }
    }
}

// ---------------------------------------------------------------------------
extern "C" void kernel_launch(void* const* d_in, const int* in_sizes, int n_in,
                              void* d_out, int out_size) {
    const float* x0 = (const float*)d_in[0];
    const float* x1 = (const float*)d_in[1];
    const float* x2 = (const float*)d_in[2];
    const float* x3 = (const float*)d_in[3];
    const float* c0 = (const float*)d_in[4];
    const float* w0 = (const float*)d_in[5];
    const float* c1 = (const float*)d_in[6];
    const float* w1 = (const float*)d_in[7];
    const float* c2 = (const float*)d_in[8];
    const float* w2 = (const float*)d_in[9];
    const float* c3 = (const float*)d_in[10];
    const float* w3 = (const float*)d_in[11];
    float* out = (float*)d_out;

    uint32_t *pW64, *pW128, *pW256, *pCt0, *pCt1, *pCt2, *pCt3, *pxT, *pxT2;
    float *pbias, *pd3, *pd2, *pd1, *pu3, *pu2, *pu1, *pu0, *poh1, *poh2, *poh3;
    cudaGetSymbolAddress((void**)&pW64,  g_W64);
    cudaGetSymbolAddress((void**)&pW128, g_W128);
    cudaGetSymbolAddress((void**)&pW256, g_W256);
    cudaGetSymbolAddress((void**)&pCt0,  g_Ct0);
    cudaGetSymbolAddress((void**)&pCt1,  g_Ct1);
    cudaGetSymbolAddress((void**)&pCt2,  g_Ct2);
    cudaGetSymbolAddress((void**)&pCt3,  g_Ct3);
    cudaGetSymbolAddress((void**)&pbias, g_bias);
    cudaGetSymbolAddress((void**)&pd3,   g_d3);
    cudaGetSymbolAddress((void**)&pd2,   g_d2);
    cudaGetSymbolAddress((void**)&pd1,   g_d1);
    cudaGetSymbolAddress((void**)&pu3,   g_u3);
    cudaGetSymbolAddress((void**)&pu2,   g_u2);
    cudaGetSymbolAddress((void**)&pu1,   g_u1);
    cudaGetSymbolAddress((void**)&pu0,   g_u0);
    cudaGetSymbolAddress((void**)&poh1,  g_oh1);
    cudaGetSymbolAddress((void**)&poh2,  g_oh2);
    cudaGetSymbolAddress((void**)&poh3,  g_oh3);
    cudaGetSymbolAddress((void**)&pxT,   g_xT);
    cudaGetSymbolAddress((void**)&pxT2,  g_xT2);

    cudaFuncSetAttribute(dec_batched_kernel,
                         cudaFuncAttributeMaxDynamicSharedMemorySize, SMEM_BYTES_INTERP);
    cudaFuncSetAttribute(mix_odd_kernel,
                         cudaFuncAttributeMaxDynamicSharedMemorySize, SMEM_BYTES_INTERP);
    cudaFuncSetAttribute(mkan_batched_kernel,
                         cudaFuncAttributeMaxDynamicSharedMemorySize, SMEM_BYTES_MKAN);

    /*0*/ fill_all_kernel<<<(86016 + 255) / 256, 256>>>(pW256, pW128, pW64);
    /*1*/ {
        PP p0 = {c0, pCt0, pbias + 0 * 128, 2};
        PP p1 = {c1, pCt1, pbias + 1 * 128, 3};
        PP p2 = {c2, pCt2, pbias + 2 * 128, 4};
        PP p3 = {c3, pCt3, pbias + 3 * 128, 5};
        prep_all_kernel<<<512, 256>>>(p0, p1, p2, p3);
    }
    /*2*/ transpose_all_kernel<<<dim3(56, 1, 128), dim3(32, 8)>>>(x1, x2, x3, pxT);
    /*3*/ {
        DP s3 = {pW256, pxT + XT256_OFF, x0, x1, pd3, pu3, 256};
        DP s2 = {pW128, pxT + XT128_OFF, x1, x2, pd2, pu2, 128};
        DP s1 = {pW64,  pxT + XT64_OFF,  x2, x3, pd1, pu1, 64};
        dec_batched_kernel<<<576, 256, SMEM_BYTES_INTERP>>>(s3, s2, s1, x3, pu0);
    }
    /*4*/ {
        MP s3 = {pu3, pCt3, pbias + 3 * 128, pd3, w3, poh3, nullptr, 640, 512};
        MP s2 = {pu2, pCt2, pbias + 2 * 128, pd2, w2, poh2, nullptr, 512, 256};
        MP s1 = {pu1, pCt1, pbias + 1 * 128, pd1, w1, poh1, nullptr, 384, 128};
        MP s0 = {pu0, pCt0, pbias + 0 * 128, x3, w0, out + OFF64, pxT2, 256, 64};
        mkan_batched_kernel<<<960, 256, SMEM_BYTES_MKAN>>>(s3, s2, s1, s0);
    }
    /*5*/ mix_odd_kernel<<<dim3(1, 128), 256, SMEM_BYTES_INTERP>>>(
              pW64, pxT2, poh1, out + OFF64, out + OFF128, pxT, 64);
    /*6*/ mix_odd_kernel<<<dim3(1, 128), 256, SMEM_BYTES_INTERP>>>(
              pW128, pxT, poh2, out + OFF128, out + OFF256, pxT2, 128);
    /*7*/ mix_odd_kernel<<<dim3(2, 128), 256, SMEM_BYTES_INTERP>>>(
              pW256, pxT2, poh3, out + OFF256, out + OFF512, nullptr, 256);

    (void)in_sizes; (void)n_in; (void)out_size;
}